// round 3
// baseline (speedup 1.0000x reference)
#include <cuda_runtime.h>
#include <cstddef>

#define B 4
#define T 2048
#define C 1024
#define H 64

// scratch for projected q, k, v: [B*T, H] each (2 MB each)
__device__ float g_q[B * T * H];
__device__ float g_k[B * T * H];
__device__ float g_v[B * T * H];

// ---------------------------------------------------------------------------
// Kernel 1: fused QKV projection.  y[row,h] = sum_c x[row,c] * W[h,c]
// grid = (128 row-tiles, 3 weight matrices), block = 256 threads
// Tiles: 64 rows x 64 h-cols, K-chunks of 64. Smem stored k-major so the
// inner loop is 2x LDS.128 + 16 FFMA per k-step.
// ---------------------------------------------------------------------------
#define RT 64
#define KT 64
#define PSTR 68   // smem row stride in floats (pad, multiple of 4)

__global__ __launch_bounds__(256) void qkv_proj(const float* __restrict__ x,
                                                const float* __restrict__ Wq,
                                                const float* __restrict__ Wk,
                                                const float* __restrict__ Wv) {
    __shared__ float xs[KT][PSTR];  // [k][row]
    __shared__ float ws[KT][PSTR];  // [k][h]

    const float* W   = (blockIdx.y == 0) ? Wq : (blockIdx.y == 1) ? Wk : Wv;
    float*       out = (blockIdx.y == 0) ? g_q : (blockIdx.y == 1) ? g_k : g_v;

    const int rowBase = blockIdx.x * RT;
    const int tid = threadIdx.x;
    const int tx = tid & 15;      // h-col group (4 cols each)
    const int ty = tid >> 4;      // row group (4 rows each)

    float acc[4][4] = {};

    for (int k0 = 0; k0 < C; k0 += KT) {
        // Load 64x64 x-tile and 64x64 W-tile, transposing into k-major smem.
        #pragma unroll
        for (int i = 0; i < 4; i++) {
            int f  = tid + i * 256;     // float4 index in tile
            int r  = f >> 4;            // tile row (0..63)
            int c4 = f & 15;            // float4 col (0..15)
            float4 xv = *(const float4*)(x + (size_t)(rowBase + r) * C + k0 + c4 * 4);
            xs[c4 * 4 + 0][r] = xv.x;
            xs[c4 * 4 + 1][r] = xv.y;
            xs[c4 * 4 + 2][r] = xv.z;
            xs[c4 * 4 + 3][r] = xv.w;
            float4 wv = *(const float4*)(W + (size_t)r * C + k0 + c4 * 4);
            ws[c4 * 4 + 0][r] = wv.x;
            ws[c4 * 4 + 1][r] = wv.y;
            ws[c4 * 4 + 2][r] = wv.z;
            ws[c4 * 4 + 3][r] = wv.w;
        }
        __syncthreads();

        #pragma unroll
        for (int kk = 0; kk < KT; kk++) {
            float4 a = *(const float4*)&xs[kk][ty * 4];
            float4 b = *(const float4*)&ws[kk][tx * 4];
            const float av[4] = {a.x, a.y, a.z, a.w};
            const float bv[4] = {b.x, b.y, b.z, b.w};
            #pragma unroll
            for (int i = 0; i < 4; i++)
                #pragma unroll
                for (int j = 0; j < 4; j++)
                    acc[i][j] += av[i] * bv[j];
        }
        __syncthreads();
    }

    #pragma unroll
    for (int i = 0; i < 4; i++) {
        int row = rowBase + ty * 4 + i;
        float4 o = {acc[i][0], acc[i][1], acc[i][2], acc[i][3]};
        *(float4*)(out + (size_t)row * H + tx * 4) = o;
    }
}

// ---------------------------------------------------------------------------
// Kernel 2: causal flash attention over the projected q/k/v.
// grid = (32 pairs, B), block = 256 threads.
// Block handles query tiles {blockIdx.x, 63 - blockIdx.x} (32 queries each)
// so every block runs exactly 65 key tiles -> perfect causal load balance.
// Thread (r = tid>>3, g = tid&7): owns query row r, output cols g*8..g*8+7,
// and S columns {g, g+8, g+16, g+24}.
// ---------------------------------------------------------------------------
#define QT 32
#define KTL 32
// softmax scale 1/sqrt(64) with log2(e) folded in so we can use exp2f
#define QSCALE 0.18033688011112042f   // 0.125 * 1.4426950408889634

__global__ __launch_bounds__(256) void attn(float* __restrict__ out) {
    __shared__ float Qs[QT][PSTR];
    __shared__ float Ks[KTL][PSTR];
    __shared__ float Vs[KTL][PSTR];
    __shared__ float Ps[QT][36];

    const int tid = threadIdx.x;
    const int r = tid >> 3;   // query row in tile
    const int g = tid & 7;    // column group
    const int bT = blockIdx.y * T;

    for (int side = 0; side < 2; side++) {
        const int qt = (side == 0) ? (int)blockIdx.x : (63 - (int)blockIdx.x);
        const int qBase = qt * QT;

        // Load + scale Q tile [32 x 64]
        #pragma unroll
        for (int i = 0; i < 2; i++) {
            int f = tid + i * 256;
            int rr = f >> 4, c4 = f & 15;
            float4 qv = *(const float4*)(g_q + (size_t)(bT + qBase + rr) * H + c4 * 4);
            qv.x *= QSCALE; qv.y *= QSCALE; qv.z *= QSCALE; qv.w *= QSCALE;
            *(float4*)&Qs[rr][c4 * 4] = qv;
        }

        float o0 = 0, o1 = 0, o2 = 0, o3 = 0, o4 = 0, o5 = 0, o6 = 0, o7 = 0;
        float m = -1e30f, l = 0.0f;

        const int nkt = qt + 1;
        for (int j = 0; j < nkt; j++) {
            const int kBase = j * KTL;

            // Load K and V tiles [32 x 64]
            #pragma unroll
            for (int i = 0; i < 2; i++) {
                int f = tid + i * 256;
                int rr = f >> 4, c4 = f & 15;
                size_t base = (size_t)(bT + kBase + rr) * H + c4 * 4;
                *(float4*)&Ks[rr][c4 * 4] = *(const float4*)(g_k + base);
                *(float4*)&Vs[rr][c4 * 4] = *(const float4*)(g_v + base);
            }
            __syncthreads();

            // S = Q K^T : 4 columns per thread
            float s0 = 0, s1 = 0, s2 = 0, s3 = 0;
            #pragma unroll
            for (int h4 = 0; h4 < 16; h4++) {
                float4 qv = *(const float4*)&Qs[r][h4 * 4];
                float4 k0 = *(const float4*)&Ks[g][h4 * 4];
                float4 k1 = *(const float4*)&Ks[g + 8][h4 * 4];
                float4 k2 = *(const float4*)&Ks[g + 16][h4 * 4];
                float4 k3 = *(const float4*)&Ks[g + 24][h4 * 4];
                s0 += qv.x * k0.x + qv.y * k0.y + qv.z * k0.z + qv.w * k0.w;
                s1 += qv.x * k1.x + qv.y * k1.y + qv.z * k1.z + qv.w * k1.w;
                s2 += qv.x * k2.x + qv.y * k2.y + qv.z * k2.z + qv.w * k2.w;
                s3 += qv.x * k3.x + qv.y * k3.y + qv.z * k3.z + qv.w * k3.w;
            }

            // Causal mask (only the diagonal tile needs it; kBase == qBase there)
            if (j == nkt - 1) {
                if (g      > r) s0 = -1e30f;
                if (g + 8  > r) s1 = -1e30f;
                if (g + 16 > r) s2 = -1e30f;
                if (g + 24 > r) s3 = -1e30f;
            }

            // Online softmax (values are already in log2 domain via QSCALE)
            float mx = fmaxf(fmaxf(s0, s1), fmaxf(s2, s3));
            mx = fmaxf(mx, __shfl_xor_sync(0xffffffffu, mx, 1, 8));
            mx = fmaxf(mx, __shfl_xor_sync(0xffffffffu, mx, 2, 8));
            mx = fmaxf(mx, __shfl_xor_sync(0xffffffffu, mx, 4, 8));
            float mnew = fmaxf(m, mx);
            float corr = exp2f(m - mnew);
            float p0 = exp2f(s0 - mnew);
            float p1 = exp2f(s1 - mnew);
            float p2 = exp2f(s2 - mnew);
            float p3 = exp2f(s3 - mnew);
            float rs = p0 + p1 + p2 + p3;
            rs += __shfl_xor_sync(0xffffffffu, rs, 1, 8);
            rs += __shfl_xor_sync(0xffffffffu, rs, 2, 8);
            rs += __shfl_xor_sync(0xffffffffu, rs, 4, 8);
            l = l * corr + rs;
            m = mnew;
            o0 *= corr; o1 *= corr; o2 *= corr; o3 *= corr;
            o4 *= corr; o5 *= corr; o6 *= corr; o7 *= corr;

            Ps[r][g]      = p0;
            Ps[r][g + 8]  = p1;
            Ps[r][g + 16] = p2;
            Ps[r][g + 24] = p3;
            __syncthreads();

            // O += P V : 8 columns per thread
            #pragma unroll
            for (int k4 = 0; k4 < 8; k4++) {
                float4 pv = *(const float4*)&Ps[r][k4 * 4];
                const float pa[4] = {pv.x, pv.y, pv.z, pv.w};
                #pragma unroll
                for (int u = 0; u < 4; u++) {
                    float p = pa[u];
                    int kk = k4 * 4 + u;
                    float4 v0 = *(const float4*)&Vs[kk][g * 8];
                    float4 v1 = *(const float4*)&Vs[kk][g * 8 + 4];
                    o0 += p * v0.x; o1 += p * v0.y; o2 += p * v0.z; o3 += p * v0.w;
                    o4 += p * v1.x; o5 += p * v1.y; o6 += p * v1.z; o7 += p * v1.w;
                }
            }
            __syncthreads();  // protect Ks/Vs/Ps before next iteration's writes
        }

        const float inv = 1.0f / l;
        size_t row = (size_t)(bT + qBase + r);
        float4 w0 = {o0 * inv, o1 * inv, o2 * inv, o3 * inv};
        float4 w1 = {o4 * inv, o5 * inv, o6 * inv, o7 * inv};
        *(float4*)(out + row * H + g * 8)     = w0;
        *(float4*)(out + row * H + g * 8 + 4) = w1;
    }
}

extern "C" void kernel_launch(void* const* d_in, const int* in_sizes, int n_in,
                              void* d_out, int out_size) {
    const float* x  = (const float*)d_in[0];
    const float* Wq = (const float*)d_in[1];
    const float* Wk = (const float*)d_in[2];
    const float* Wv = (const float*)d_in[3];
    float* out = (float*)d_out;

    qkv_proj<<<dim3(B * T / RT, 3), 256>>>(x, Wq, Wk, Wv);
    attn<<<dim3(32, B), 256>>>(out);
}

// round 4
// speedup vs baseline: 1.0056x; 1.0056x over previous
#include <cuda_runtime.h>
#include <cstddef>

#define B 4
#define T 2048
#define C 1024
#define H 64

// scratch for projected q, k, v: [B*T, H] each (2 MB each)
__device__ float g_q[B * T * H];
__device__ float g_k[B * T * H];
__device__ float g_v[B * T * H];

// ---------------------------------------------------------------------------
// Kernel 1: fused QKV projection.  y[row,h] = sum_c x[row,c] * W[h,c]
// grid = (128 row-tiles, 3 weight matrices), block = 256 threads
// ---------------------------------------------------------------------------
#define RT 64
#define KT 64
#define PSTR 68   // smem row stride in floats

__global__ __launch_bounds__(256) void qkv_proj(const float* __restrict__ x,
                                                const float* __restrict__ Wq,
                                                const float* __restrict__ Wk,
                                                const float* __restrict__ Wv) {
    __shared__ float xs[KT][PSTR];  // [k][row]
    __shared__ float ws[KT][PSTR];  // [k][h]

    const float* W   = (blockIdx.y == 0) ? Wq : (blockIdx.y == 1) ? Wk : Wv;
    float*       out = (blockIdx.y == 0) ? g_q : (blockIdx.y == 1) ? g_k : g_v;

    const int rowBase = blockIdx.x * RT;
    const int tid = threadIdx.x;
    const int tx = tid & 15;      // h-col group (4 cols each)
    const int ty = tid >> 4;      // row group (4 rows each)

    float acc[4][4] = {};

    for (int k0 = 0; k0 < C; k0 += KT) {
        #pragma unroll
        for (int i = 0; i < 4; i++) {
            int f  = tid + i * 256;
            int r  = f >> 4;
            int c4 = f & 15;
            float4 xv = *(const float4*)(x + (size_t)(rowBase + r) * C + k0 + c4 * 4);
            xs[c4 * 4 + 0][r] = xv.x;
            xs[c4 * 4 + 1][r] = xv.y;
            xs[c4 * 4 + 2][r] = xv.z;
            xs[c4 * 4 + 3][r] = xv.w;
            float4 wv = *(const float4*)(W + (size_t)r * C + k0 + c4 * 4);
            ws[c4 * 4 + 0][r] = wv.x;
            ws[c4 * 4 + 1][r] = wv.y;
            ws[c4 * 4 + 2][r] = wv.z;
            ws[c4 * 4 + 3][r] = wv.w;
        }
        __syncthreads();

        #pragma unroll
        for (int kk = 0; kk < KT; kk++) {
            float4 a = *(const float4*)&xs[kk][ty * 4];
            float4 b = *(const float4*)&ws[kk][tx * 4];
            const float av[4] = {a.x, a.y, a.z, a.w};
            const float bv[4] = {b.x, b.y, b.z, b.w};
            #pragma unroll
            for (int i = 0; i < 4; i++)
                #pragma unroll
                for (int j = 0; j < 4; j++)
                    acc[i][j] += av[i] * bv[j];
        }
        __syncthreads();
    }

    #pragma unroll
    for (int i = 0; i < 4; i++) {
        int row = rowBase + ty * 4 + i;
        float4 o = {acc[i][0], acc[i][1], acc[i][2], acc[i][3]};
        *(float4*)(out + (size_t)row * H + tx * 4) = o;
    }
}

// ---------------------------------------------------------------------------
// Kernel 2: causal flash attention, v2.
// grid = (64 q-tiles, B) launched longest-first, block = 256 threads.
// QT=32 queries per block, KTL=64 keys per iteration, double-buffered K/V.
// Thread (r = tid>>3, g = tid&7):
//   - S columns  g + 8*jj,  jj = 0..7     (64 cols per row, 8 threads/row)
//   - O columns  4g..4g+3 and 32+4g..32+4g+3 (bank-conflict-free V reads)
// Smem (dynamic, 87.5 KB): Qs[32][68], Ps[32][72], K/V[2][64][68]
// ---------------------------------------------------------------------------
#define QT 32
#define KTL 64
#define PSSTR 72
// softmax scale 1/sqrt(64) with log2(e) folded in so we can use exp2f
#define QSCALE 0.18033688011112042f   // 0.125 * 1.4426950408889634

#define SM_QS   0
#define SM_PS   (32 * 68)
#define SM_K    (SM_PS + 32 * PSSTR)
#define SM_V    (SM_K + 2 * 64 * 68)
#define SM_TOT  (SM_V + 2 * 64 * 68)   // 21888 floats = 87552 bytes

__global__ __launch_bounds__(256, 2) void attn(float* __restrict__ out) {
    extern __shared__ float sm[];
    float* Qs  = sm + SM_QS;   // [32][68]
    float* Ps  = sm + SM_PS;   // [32][PSSTR]
    float* Ksm = sm + SM_K;    // [2][64][68]
    float* Vsm = sm + SM_V;    // [2][64][68]

    const int tid = threadIdx.x;
    const int r = tid >> 3;   // query row in tile
    const int g = tid & 7;    // column group
    const int bT = blockIdx.y * T;

    const int qt = 63 - (int)blockIdx.x;   // longest blocks launch first
    const int qBase = qt * QT;
    const int keys = qBase + QT;
    const int nkt = (keys + KTL - 1) / KTL;

    // per-thread tile-load coordinates (4 float4 rows per matrix)
    const int lr0 = tid >> 4;          // 0..15
    const int lc4 = (tid & 15) * 4;    // 0..60

    // Load + scale Q tile [32 x 64] and preload K/V tile 0 into buffer 0
    #pragma unroll
    for (int i = 0; i < 2; i++) {
        int rr = lr0 + i * 16;
        float4 qv = *(const float4*)(g_q + (size_t)(bT + qBase + rr) * H + lc4);
        qv.x *= QSCALE; qv.y *= QSCALE; qv.z *= QSCALE; qv.w *= QSCALE;
        *(float4*)&Qs[rr * 68 + lc4] = qv;
    }
    #pragma unroll
    for (int i = 0; i < 4; i++) {
        int rr = lr0 + i * 16;
        size_t gb = (size_t)(bT + rr) * H + lc4;
        *(float4*)&Ksm[rr * 68 + lc4] = *(const float4*)(g_k + gb);
        *(float4*)&Vsm[rr * 68 + lc4] = *(const float4*)(g_v + gb);
    }
    __syncthreads();

    float o[8] = {};
    float m = -1e30f, l = 0.0f;

    for (int j = 0; j < nkt; j++) {
        const int cur = j & 1;
        const float* Kc = Ksm + cur * (64 * 68);
        const float* Vc = Vsm + cur * (64 * 68);

        // Prefetch next K/V tile into registers (latency hidden under S)
        float4 kp[4], vp[4];
        const bool pf = (j + 1 < nkt);
        if (pf) {
            const int kb2 = (j + 1) * KTL;
            #pragma unroll
            for (int i = 0; i < 4; i++) {
                int rr = lr0 + i * 16;
                size_t gb = (size_t)(bT + kb2 + rr) * H + lc4;
                kp[i] = *(const float4*)(g_k + gb);
                vp[i] = *(const float4*)(g_v + gb);
            }
        }

        // S = Q K^T : 8 columns per thread (cols g + 8*jj)
        float s[8] = {};
        #pragma unroll
        for (int h4 = 0; h4 < 16; h4++) {
            float4 qv = *(const float4*)&Qs[r * 68 + h4 * 4];
            #pragma unroll
            for (int jj = 0; jj < 8; jj++) {
                float4 kv = *(const float4*)&Kc[(g + 8 * jj) * 68 + h4 * 4];
                s[jj] += qv.x * kv.x + qv.y * kv.y + qv.z * kv.z + qv.w * kv.w;
            }
        }

        // Causal mask — only ever needed on the last iteration
        if (j == nkt - 1) {
            const int kBase = j * KTL;
            #pragma unroll
            for (int jj = 0; jj < 8; jj++)
                if (kBase + g + 8 * jj > qBase + r) s[jj] = -1e30f;
        }

        // Online softmax (log2 domain via QSCALE)
        float mx = s[0];
        #pragma unroll
        for (int jj = 1; jj < 8; jj++) mx = fmaxf(mx, s[jj]);
        mx = fmaxf(mx, __shfl_xor_sync(0xffffffffu, mx, 1, 8));
        mx = fmaxf(mx, __shfl_xor_sync(0xffffffffu, mx, 2, 8));
        mx = fmaxf(mx, __shfl_xor_sync(0xffffffffu, mx, 4, 8));
        float mnew = fmaxf(m, mx);
        float corr = exp2f(m - mnew);
        float rs = 0.0f;
        float p[8];
        #pragma unroll
        for (int jj = 0; jj < 8; jj++) {
            p[jj] = exp2f(s[jj] - mnew);
            rs += p[jj];
        }
        rs += __shfl_xor_sync(0xffffffffu, rs, 1, 8);
        rs += __shfl_xor_sync(0xffffffffu, rs, 2, 8);
        rs += __shfl_xor_sync(0xffffffffu, rs, 4, 8);
        l = l * corr + rs;
        m = mnew;
        #pragma unroll
        for (int u = 0; u < 8; u++) o[u] *= corr;

        // Publish P and stage the prefetched tile into the alternate buffer
        #pragma unroll
        for (int jj = 0; jj < 8; jj++) Ps[r * PSSTR + g + 8 * jj] = p[jj];
        if (pf) {
            float* Kn = Ksm + (1 - cur) * (64 * 68);
            float* Vn = Vsm + (1 - cur) * (64 * 68);
            #pragma unroll
            for (int i = 0; i < 4; i++) {
                int rr = lr0 + i * 16;
                *(float4*)&Kn[rr * 68 + lc4] = kp[i];
                *(float4*)&Vn[rr * 68 + lc4] = vp[i];
            }
        }
        __syncthreads();   // P + next tile visible

        // O += P V : cols 4g..4g+3 and 32+4g..32+4g+3 (conflict-free)
        #pragma unroll
        for (int k4 = 0; k4 < 16; k4++) {
            float4 pv = *(const float4*)&Ps[r * PSSTR + k4 * 4];
            const float pa[4] = {pv.x, pv.y, pv.z, pv.w};
            #pragma unroll
            for (int u = 0; u < 4; u++) {
                const float pp = pa[u];
                const int kk = k4 * 4 + u;
                float4 v0 = *(const float4*)&Vc[kk * 68 + g * 4];
                float4 v1 = *(const float4*)&Vc[kk * 68 + 32 + g * 4];
                o[0] += pp * v0.x; o[1] += pp * v0.y;
                o[2] += pp * v0.z; o[3] += pp * v0.w;
                o[4] += pp * v1.x; o[5] += pp * v1.y;
                o[6] += pp * v1.z; o[7] += pp * v1.w;
            }
        }
        __syncthreads();   // PV done: Ps / Vs[cur] free for next iteration
    }

    const float inv = 1.0f / l;
    size_t row = (size_t)(bT + qBase + r);
    float4 w0 = {o[0] * inv, o[1] * inv, o[2] * inv, o[3] * inv};
    float4 w1 = {o[4] * inv, o[5] * inv, o[6] * inv, o[7] * inv};
    *(float4*)(out + row * H + g * 4)      = w0;
    *(float4*)(out + row * H + 32 + g * 4) = w1;
}

extern "C" void kernel_launch(void* const* d_in, const int* in_sizes, int n_in,
                              void* d_out, int out_size) {
    const float* x  = (const float*)d_in[0];
    const float* Wq = (const float*)d_in[1];
    const float* Wk = (const float*)d_in[2];
    const float* Wv = (const float*)d_in[3];
    float* out = (float*)d_out;

    static_assert(SM_TOT * 4 == 87552, "smem layout");
    cudaFuncSetAttribute(attn, cudaFuncAttributeMaxDynamicSharedMemorySize,
                         SM_TOT * 4);

    qkv_proj<<<dim3(B * T / RT, 3), 256>>>(x, Wq, Wk, Wv);
    attn<<<dim3(64, B), 256, SM_TOT * 4>>>(out);
}

// round 6
// speedup vs baseline: 1.2756x; 1.2685x over previous
#include <cuda_runtime.h>
#include <cuda_bf16.h>
#include <cstdint>
#include <cstddef>

#define B 4
#define T 2048
#define C 1024
#define H 64
#define NROW (B * T)

// fp32 projected q/k/v (consumed by attn)
__device__ float g_q[NROW * H];
__device__ float g_k[NROW * H];
__device__ float g_v[NROW * H];
// bf16 hi/lo split operands for tensor-core projection
__device__ __nv_bfloat16 g_xh[NROW * C];
__device__ __nv_bfloat16 g_xl[NROW * C];
__device__ __nv_bfloat16 g_wh[192 * C];   // rows 0-63 Wq, 64-127 Wk, 128-191 Wv
__device__ __nv_bfloat16 g_wl[192 * C];

// ---------------------------------------------------------------------------
// Baseline-PTX helpers (sm_80+ features only — NO tcgen05 on this toolchain)
// ---------------------------------------------------------------------------
__device__ __forceinline__ uint32_t smem_u32(const void* p) {
    uint32_t a;
    asm("{ .reg .u64 t; cvta.to.shared.u64 t, %1; cvt.u32.u64 %0, t; }"
        : "=r"(a) : "l"(p));
    return a;
}
__device__ __forceinline__ void cp16(uint32_t dst, const void* src) {
    asm volatile("cp.async.cg.shared.global [%0], [%1], 16;"
                 :: "r"(dst), "l"(src) : "memory");
}
__device__ __forceinline__ void ldsm4(uint32_t* r, uint32_t addr) {
    asm volatile("ldmatrix.sync.aligned.m8n8.x4.shared.b16 {%0,%1,%2,%3}, [%4];"
                 : "=r"(r[0]), "=r"(r[1]), "=r"(r[2]), "=r"(r[3]) : "r"(addr));
}
__device__ __forceinline__ void mma_bf16(float* d, const uint32_t* a,
                                         const uint32_t* b) {
    asm volatile(
        "mma.sync.aligned.m16n8k16.row.col.f32.bf16.bf16.f32 "
        "{%0,%1,%2,%3}, {%4,%5,%6,%7}, {%8,%9}, {%0,%1,%2,%3};"
        : "+f"(d[0]), "+f"(d[1]), "+f"(d[2]), "+f"(d[3])
        : "r"(a[0]), "r"(a[1]), "r"(a[2]), "r"(a[3]), "r"(b[0]), "r"(b[1]));
}

// ---------------------------------------------------------------------------
// Kernel 0: split x and packed W into bf16 hi/lo scratch
// ---------------------------------------------------------------------------
#define X4 (NROW * C / 4)
#define W4 (192 * C / 4)

__global__ __launch_bounds__(256) void convert_split(const float* __restrict__ x,
                                                     const float* __restrict__ Wq,
                                                     const float* __restrict__ Wk,
                                                     const float* __restrict__ Wv) {
    int i = blockIdx.x * 256 + threadIdx.x;
    if (i >= X4 + W4) return;
    float4 v;
    __nv_bfloat16 *dh, *dl;
    size_t off;
    if (i < X4) {
        v = ((const float4*)x)[i];
        dh = g_xh; dl = g_xl; off = (size_t)i * 4;
    } else {
        int r = i - X4;
        int wrow = r >> 8;            // 0..191
        int c4 = r & 255;
        const float* src = (wrow < 64)  ? Wq + (size_t)wrow * C
                         : (wrow < 128) ? Wk + (size_t)(wrow - 64) * C
                                        : Wv + (size_t)(wrow - 128) * C;
        v = ((const float4*)src)[c4];
        dh = g_wh; dl = g_wl; off = (size_t)wrow * C + (size_t)c4 * 4;
    }
    const float a[4] = {v.x, v.y, v.z, v.w};
    __nv_bfloat16 h[4], l[4];
#pragma unroll
    for (int j = 0; j < 4; j++) {
        h[j] = __float2bfloat16(a[j]);
        l[j] = __float2bfloat16(a[j] - __bfloat162float(h[j]));
    }
    __nv_bfloat162* ph = (__nv_bfloat162*)(dh + off);
    __nv_bfloat162* pl = (__nv_bfloat162*)(dl + off);
    ph[0] = {h[0], h[1]}; ph[1] = {h[2], h[3]};
    pl[0] = {l[0], l[1]}; pl[1] = {l[2], l[3]};
}

// ---------------------------------------------------------------------------
// Kernel 1: QKV projection on HMMA (mma.sync bf16, hi/lo split).
// grid = (64 M-tiles of 128 rows, 3 weights), 256 threads = 8 warps (4m x 2n).
// CTA tile 128x64, K staged 64/iter via cp.async double buffer.
// Smem tiles padded to stride 72 halves (144B) -> conflict-free ldmatrix.
// ---------------------------------------------------------------------------
#define ASTR 72
#define AH_OFF 0
#define AL_OFF 9216        // 128*72
#define BH_OFF 18432
#define BL_OFF 23040       // +64*72
#define STG_ELEMS 27648    // bf16 elems per stage
#define PROJ_SMEM (2 * STG_ELEMS * 2)   // 110592 bytes

__global__ __launch_bounds__(256, 2) void qkv_mma() {
    extern __shared__ __nv_bfloat16 smb[];
    const uint32_t su = smem_u32(smb);
    const int tid = threadIdx.x;
    const int lane = tid & 31;
    const int wid = tid >> 5;
    const int wm = wid & 3;        // m block: rows wm*32..wm*32+31
    const int wn = wid >> 2;       // n block: cols wn*32..wn*32+31
    const int w = blockIdx.y;
    const int rowBase = blockIdx.x * 128;

    const __nv_bfloat16* __restrict__ Bh = g_wh + (size_t)w * 64 * C;
    const __nv_bfloat16* __restrict__ Bl = g_wl + (size_t)w * 64 * C;
    float* outp = (w == 0) ? g_q : (w == 1) ? g_k : g_v;

    // ldmatrix per-lane byte offsets
    // A (m16k16, row-major): lanes 0-15 -> row lane, k+0; lanes 16-31 -> row lane-16, k+8
    const uint32_t aoff = (uint32_t)((lane & 15) * ASTR + ((lane >> 4) << 3)) * 2;
    // B (n8k16 pairs): lanes 0-7:(n,k0) 8-15:(n,k8) 16-23:(n+8,k0) 24-31:(n+8,k8)
    const uint32_t boff = (uint32_t)(((lane & 7) + ((lane >> 4) << 3)) * ASTR +
                                     (((lane >> 3) & 1) << 3)) * 2;

    float acc[2][4][4] = {};

    auto load_stage = [&](int buf, int k0) {
        const uint32_t sb = su + (uint32_t)buf * (STG_ELEMS * 2);
#pragma unroll
        for (int i = 0; i < 4; i++) {
            int idx = tid + i * 256;
            int row = idx >> 3, c = (idx & 7) * 8;
            const size_t gs = (size_t)(rowBase + row) * C + k0 + c;
            const uint32_t d = (uint32_t)(row * ASTR + c) * 2;
            cp16(sb + AH_OFF * 2 + d, g_xh + gs);
            cp16(sb + AL_OFF * 2 + d, g_xl + gs);
        }
#pragma unroll
        for (int i = 0; i < 2; i++) {
            int idx = tid + i * 256;
            int row = idx >> 3, c = (idx & 7) * 8;
            const size_t gs = (size_t)row * C + k0 + c;
            const uint32_t d = (uint32_t)(row * ASTR + c) * 2;
            cp16(sb + BH_OFF * 2 + d, Bh + gs);
            cp16(sb + BL_OFF * 2 + d, Bl + gs);
        }
        asm volatile("cp.async.commit_group;" ::: "memory");
    };

    auto compute = [&](int buf) {
        const uint32_t sb = su + (uint32_t)buf * (STG_ELEMS * 2);
#pragma unroll
        for (int kk = 0; kk < 64; kk += 16) {
            uint32_t ah[2][4], al[2][4], bh[8], bl[8];
#pragma unroll
            for (int mi = 0; mi < 2; mi++) {
                uint32_t base = sb + (uint32_t)((wm * 32 + mi * 16) * ASTR + kk) * 2 + aoff;
                ldsm4(ah[mi], base + AH_OFF * 2);
                ldsm4(al[mi], base + AL_OFF * 2);
            }
#pragma unroll
            for (int n2 = 0; n2 < 2; n2++) {
                uint32_t base = sb + (uint32_t)((wn * 32 + n2 * 16) * ASTR + kk) * 2 + boff;
                ldsm4(bh + n2 * 4, base + BH_OFF * 2);
                ldsm4(bl + n2 * 4, base + BL_OFF * 2);
            }
#pragma unroll
            for (int mi = 0; mi < 2; mi++)
#pragma unroll
                for (int nf = 0; nf < 4; nf++) {
                    float* d = acc[mi][nf];
                    mma_bf16(d, ah[mi], bh + nf * 2);   // hi*hi
                    mma_bf16(d, ah[mi], bl + nf * 2);   // hi*lo
                    mma_bf16(d, al[mi], bh + nf * 2);   // lo*hi
                }
        }
    };

    load_stage(0, 0);
    load_stage(1, 64);

    for (int j = 0; j < 16; j++) {
        if (j < 14) asm volatile("cp.async.wait_group 1;" ::: "memory");
        else        asm volatile("cp.async.wait_group 0;" ::: "memory");
        __syncthreads();
        compute(j & 1);
        if (j + 2 < 16) {
            __syncthreads();                 // everyone done reading buf j&1
            load_stage(j & 1, (j + 2) * 64);
        }
    }

    // epilogue: c-frag (m16n8): c0,c1 = row g, cols 2t,2t+1; c2,c3 = row g+8
    const int g2 = lane >> 2;
    const int t2 = (lane & 3) * 2;
#pragma unroll
    for (int mi = 0; mi < 2; mi++)
#pragma unroll
        for (int nf = 0; nf < 4; nf++) {
            const int row0 = rowBase + wm * 32 + mi * 16 + g2;
            const int col = wn * 32 + nf * 8 + t2;
            float2 v0 = {acc[mi][nf][0], acc[mi][nf][1]};
            float2 v1 = {acc[mi][nf][2], acc[mi][nf][3]};
            *(float2*)(outp + (size_t)row0 * H + col) = v0;
            *(float2*)(outp + (size_t)(row0 + 8) * H + col) = v1;
        }
}

// ---------------------------------------------------------------------------
// Kernel 2: causal flash attention (unchanged, known-good 244 us)
// ---------------------------------------------------------------------------
#define QT 32
#define KTL 64
#define PSSTR 72
#define QSCALE 0.18033688011112042f   // 0.125 * log2(e)

#define SM_QS   0
#define SM_PS   (32 * 68)
#define SM_K    (SM_PS + 32 * PSSTR)
#define SM_V    (SM_K + 2 * 64 * 68)
#define SM_TOT  (SM_V + 2 * 64 * 68)   // 21888 floats = 87552 bytes

__global__ __launch_bounds__(256, 2) void attn(float* __restrict__ out) {
    extern __shared__ float smf[];
    float* Qs  = smf + SM_QS;
    float* Ps  = smf + SM_PS;
    float* Ksm = smf + SM_K;
    float* Vsm = smf + SM_V;

    const int tid = threadIdx.x;
    const int r = tid >> 3;
    const int g = tid & 7;
    const int bT = blockIdx.y * T;

    const int qt = 63 - (int)blockIdx.x;
    const int qBase = qt * QT;
    const int keys = qBase + QT;
    const int nkt = (keys + KTL - 1) / KTL;

    const int lr0 = tid >> 4;
    const int lc4 = (tid & 15) * 4;

#pragma unroll
    for (int i = 0; i < 2; i++) {
        int rr = lr0 + i * 16;
        float4 qv = *(const float4*)(g_q + (size_t)(bT + qBase + rr) * H + lc4);
        qv.x *= QSCALE; qv.y *= QSCALE; qv.z *= QSCALE; qv.w *= QSCALE;
        *(float4*)&Qs[rr * 68 + lc4] = qv;
    }
#pragma unroll
    for (int i = 0; i < 4; i++) {
        int rr = lr0 + i * 16;
        size_t gb = (size_t)(bT + rr) * H + lc4;
        *(float4*)&Ksm[rr * 68 + lc4] = *(const float4*)(g_k + gb);
        *(float4*)&Vsm[rr * 68 + lc4] = *(const float4*)(g_v + gb);
    }
    __syncthreads();

    float o[8] = {};
    float m = -1e30f, l = 0.0f;

    for (int j = 0; j < nkt; j++) {
        const int cur = j & 1;
        const float* Kc = Ksm + cur * (64 * 68);
        const float* Vc = Vsm + cur * (64 * 68);

        float4 kp[4], vp[4];
        const bool pf = (j + 1 < nkt);
        if (pf) {
            const int kb2 = (j + 1) * KTL;
#pragma unroll
            for (int i = 0; i < 4; i++) {
                int rr = lr0 + i * 16;
                size_t gb = (size_t)(bT + kb2 + rr) * H + lc4;
                kp[i] = *(const float4*)(g_k + gb);
                vp[i] = *(const float4*)(g_v + gb);
            }
        }

        float s[8] = {};
#pragma unroll
        for (int h4 = 0; h4 < 16; h4++) {
            float4 qv = *(const float4*)&Qs[r * 68 + h4 * 4];
#pragma unroll
            for (int jj = 0; jj < 8; jj++) {
                float4 kv = *(const float4*)&Kc[(g + 8 * jj) * 68 + h4 * 4];
                s[jj] += qv.x * kv.x + qv.y * kv.y + qv.z * kv.z + qv.w * kv.w;
            }
        }

        if (j == nkt - 1) {
            const int kBase = j * KTL;
#pragma unroll
            for (int jj = 0; jj < 8; jj++)
                if (kBase + g + 8 * jj > qBase + r) s[jj] = -1e30f;
        }

        float mx = s[0];
#pragma unroll
        for (int jj = 1; jj < 8; jj++) mx = fmaxf(mx, s[jj]);
        mx = fmaxf(mx, __shfl_xor_sync(0xffffffffu, mx, 1, 8));
        mx = fmaxf(mx, __shfl_xor_sync(0xffffffffu, mx, 2, 8));
        mx = fmaxf(mx, __shfl_xor_sync(0xffffffffu, mx, 4, 8));
        float mnew = fmaxf(m, mx);
        float corr = exp2f(m - mnew);
        float rs = 0.0f;
        float p[8];
#pragma unroll
        for (int jj = 0; jj < 8; jj++) {
            p[jj] = exp2f(s[jj] - mnew);
            rs += p[jj];
        }
        rs += __shfl_xor_sync(0xffffffffu, rs, 1, 8);
        rs += __shfl_xor_sync(0xffffffffu, rs, 2, 8);
        rs += __shfl_xor_sync(0xffffffffu, rs, 4, 8);
        l = l * corr + rs;
        m = mnew;
#pragma unroll
        for (int u = 0; u < 8; u++) o[u] *= corr;

#pragma unroll
        for (int jj = 0; jj < 8; jj++) Ps[r * PSSTR + g + 8 * jj] = p[jj];
        if (pf) {
            float* Kn = Ksm + (1 - cur) * (64 * 68);
            float* Vn = Vsm + (1 - cur) * (64 * 68);
#pragma unroll
            for (int i = 0; i < 4; i++) {
                int rr = lr0 + i * 16;
                *(float4*)&Kn[rr * 68 + lc4] = kp[i];
                *(float4*)&Vn[rr * 68 + lc4] = vp[i];
            }
        }
        __syncthreads();

#pragma unroll
        for (int k4 = 0; k4 < 16; k4++) {
            float4 pv = *(const float4*)&Ps[r * PSSTR + k4 * 4];
            const float pa[4] = {pv.x, pv.y, pv.z, pv.w};
#pragma unroll
            for (int u = 0; u < 4; u++) {
                const float pp = pa[u];
                const int kk = k4 * 4 + u;
                float4 v0 = *(const float4*)&Vc[kk * 68 + g * 4];
                float4 v1 = *(const float4*)&Vc[kk * 68 + 32 + g * 4];
                o[0] += pp * v0.x; o[1] += pp * v0.y;
                o[2] += pp * v0.z; o[3] += pp * v0.w;
                o[4] += pp * v1.x; o[5] += pp * v1.y;
                o[6] += pp * v1.z; o[7] += pp * v1.w;
            }
        }
        __syncthreads();
    }

    const float inv = 1.0f / l;
    size_t row = (size_t)(bT + qBase + r);
    float4 w0 = {o[0] * inv, o[1] * inv, o[2] * inv, o[3] * inv};
    float4 w1 = {o[4] * inv, o[5] * inv, o[6] * inv, o[7] * inv};
    *(float4*)(out + row * H + g * 4)      = w0;
    *(float4*)(out + row * H + 32 + g * 4) = w1;
}

extern "C" void kernel_launch(void* const* d_in, const int* in_sizes, int n_in,
                              void* d_out, int out_size) {
    const float* x  = (const float*)d_in[0];
    const float* Wq = (const float*)d_in[1];
    const float* Wk = (const float*)d_in[2];
    const float* Wv = (const float*)d_in[3];
    float* out = (float*)d_out;

    static_assert(SM_TOT * 4 == 87552, "attn smem layout");
    cudaFuncSetAttribute(attn, cudaFuncAttributeMaxDynamicSharedMemorySize,
                         SM_TOT * 4);
    cudaFuncSetAttribute(qkv_mma, cudaFuncAttributeMaxDynamicSharedMemorySize,
                         PROJ_SMEM);

    convert_split<<<(X4 + W4 + 255) / 256, 256>>>(x, Wq, Wk, Wv);
    qkv_mma<<<dim3(64, 3), 256, PROJ_SMEM>>>();
    attn<<<dim3(64, B), 256, SM_TOT * 4>>>(out);
}

// round 7
// speedup vs baseline: 3.5575x; 2.7890x over previous
#include <cuda_runtime.h>
#include <cuda_bf16.h>
#include <cstdint>
#include <cstddef>

#define B 4
#define T 2048
#define C 1024
#define H 64
#define NROW (B * T)
#define QSCALE 0.18033688011112042f   // 0.125 * log2(e)

// bf16 hi/lo split operands for tensor-core projection
__device__ __align__(16) __nv_bfloat16 g_xh[NROW * C];
__device__ __align__(16) __nv_bfloat16 g_xl[NROW * C];
__device__ __align__(16) __nv_bfloat16 g_wh[192 * C];   // 0-63 Wq, 64-127 Wk, 128-191 Wv
__device__ __align__(16) __nv_bfloat16 g_wl[192 * C];
// projected q/k (bf16 hi/lo, [row][h]; q pre-scaled by QSCALE) and transposed v ([h][row])
__device__ __align__(16) __nv_bfloat16 g_qh[NROW * H];
__device__ __align__(16) __nv_bfloat16 g_ql[NROW * H];
__device__ __align__(16) __nv_bfloat16 g_kh[NROW * H];
__device__ __align__(16) __nv_bfloat16 g_kl[NROW * H];
__device__ __align__(16) __nv_bfloat16 g_vth[H * NROW];
__device__ __align__(16) __nv_bfloat16 g_vtl[H * NROW];

// ---------------------------------------------------------------------------
// Baseline-PTX helpers (sm_80+ features only — NO tcgen05 on this toolchain)
// ---------------------------------------------------------------------------
__device__ __forceinline__ uint32_t smem_u32(const void* p) {
    uint32_t a;
    asm("{ .reg .u64 t; cvta.to.shared.u64 t, %1; cvt.u32.u64 %0, t; }"
        : "=r"(a) : "l"(p));
    return a;
}
__device__ __forceinline__ void cp16(uint32_t dst, const void* src) {
    asm volatile("cp.async.cg.shared.global [%0], [%1], 16;"
                 :: "r"(dst), "l"(src) : "memory");
}
#define CP_COMMIT() asm volatile("cp.async.commit_group;" ::: "memory")
#define CP_WAIT1()  asm volatile("cp.async.wait_group 1;" ::: "memory")
#define CP_WAIT0()  asm volatile("cp.async.wait_group 0;" ::: "memory")
__device__ __forceinline__ void ldsm4(uint32_t* r, uint32_t addr) {
    asm volatile("ldmatrix.sync.aligned.m8n8.x4.shared.b16 {%0,%1,%2,%3}, [%4];"
                 : "=r"(r[0]), "=r"(r[1]), "=r"(r[2]), "=r"(r[3]) : "r"(addr));
}
__device__ __forceinline__ void mma_bf16(float* d, const uint32_t* a,
                                         const uint32_t* b) {
    asm volatile(
        "mma.sync.aligned.m16n8k16.row.col.f32.bf16.bf16.f32 "
        "{%0,%1,%2,%3}, {%4,%5,%6,%7}, {%8,%9}, {%0,%1,%2,%3};"
        : "+f"(d[0]), "+f"(d[1]), "+f"(d[2]), "+f"(d[3])
        : "r"(a[0]), "r"(a[1]), "r"(a[2]), "r"(a[3]), "r"(b[0]), "r"(b[1]));
}
__device__ __forceinline__ void split1(float v, __nv_bfloat16& h, __nv_bfloat16& l) {
    h = __float2bfloat16(v);
    l = __float2bfloat16(v - __bfloat162float(h));
}
__device__ __forceinline__ uint32_t bf2pack(__nv_bfloat16 lo, __nv_bfloat16 hi) {
    __nv_bfloat162 t{lo, hi};
    return *reinterpret_cast<uint32_t*>(&t);
}

// ---------------------------------------------------------------------------
// Kernel 0: split x and packed W into bf16 hi/lo scratch
// ---------------------------------------------------------------------------
#define X4 (NROW * C / 4)
#define W4 (192 * C / 4)

__global__ __launch_bounds__(256) void convert_split(const float* __restrict__ x,
                                                     const float* __restrict__ Wq,
                                                     const float* __restrict__ Wk,
                                                     const float* __restrict__ Wv) {
    int i = blockIdx.x * 256 + threadIdx.x;
    if (i >= X4 + W4) return;
    float4 v;
    __nv_bfloat16 *dh, *dl;
    size_t off;
    if (i < X4) {
        v = ((const float4*)x)[i];
        dh = g_xh; dl = g_xl; off = (size_t)i * 4;
    } else {
        int r = i - X4;
        int wrow = r >> 8;            // 0..191
        int c4 = r & 255;
        const float* src = (wrow < 64)  ? Wq + (size_t)wrow * C
                         : (wrow < 128) ? Wk + (size_t)(wrow - 64) * C
                                        : Wv + (size_t)(wrow - 128) * C;
        v = ((const float4*)src)[c4];
        dh = g_wh; dl = g_wl; off = (size_t)wrow * C + (size_t)c4 * 4;
    }
    const float a[4] = {v.x, v.y, v.z, v.w};
    __nv_bfloat16 h[4], l[4];
#pragma unroll
    for (int j = 0; j < 4; j++) split1(a[j], h[j], l[j]);
    __nv_bfloat162* ph = (__nv_bfloat162*)(dh + off);
    __nv_bfloat162* pl = (__nv_bfloat162*)(dl + off);
    ph[0] = {h[0], h[1]}; ph[1] = {h[2], h[3]};
    pl[0] = {l[0], l[1]}; pl[1] = {l[2], l[3]};
}

// ---------------------------------------------------------------------------
// Kernel 1: QKV projection on HMMA (mma.sync bf16, hi/lo split).
// grid = (64 M-tiles of 128 rows, 3 weights), 256 threads = 8 warps (4m x 2n).
// Epilogue writes bf16 hi/lo: Q scaled by QSCALE, V transposed to [h][row].
// ---------------------------------------------------------------------------
#define ASTR 72
#define AH_OFF 0
#define AL_OFF 9216        // 128*72
#define BH_OFF 18432
#define BL_OFF 23040       // +64*72
#define STG_ELEMS 27648    // bf16 elems per stage
#define PROJ_SMEM (2 * STG_ELEMS * 2)   // 110592 bytes

__global__ __launch_bounds__(256, 2) void qkv_mma() {
    extern __shared__ __nv_bfloat16 smb[];
    const uint32_t su = smem_u32(smb);
    const int tid = threadIdx.x;
    const int lane = tid & 31;
    const int wid = tid >> 5;
    const int wm = wid & 3;        // m block: rows wm*32..wm*32+31
    const int wn = wid >> 2;       // n block: cols wn*32..wn*32+31
    const int w = blockIdx.y;
    const int rowBase = blockIdx.x * 128;

    const __nv_bfloat16* __restrict__ Bh = g_wh + (size_t)w * 64 * C;
    const __nv_bfloat16* __restrict__ Bl = g_wl + (size_t)w * 64 * C;

    const uint32_t aoff = (uint32_t)((lane & 15) * ASTR + ((lane >> 4) << 3)) * 2;
    const uint32_t boff = (uint32_t)(((lane & 7) + ((lane >> 4) << 3)) * ASTR +
                                     (((lane >> 3) & 1) << 3)) * 2;

    float acc[2][4][4] = {};

    auto load_stage = [&](int buf, int k0) {
        const uint32_t sb = su + (uint32_t)buf * (STG_ELEMS * 2);
#pragma unroll
        for (int i = 0; i < 4; i++) {
            int idx = tid + i * 256;
            int row = idx >> 3, c = (idx & 7) * 8;
            const size_t gs = (size_t)(rowBase + row) * C + k0 + c;
            const uint32_t d = (uint32_t)(row * ASTR + c) * 2;
            cp16(sb + AH_OFF * 2 + d, g_xh + gs);
            cp16(sb + AL_OFF * 2 + d, g_xl + gs);
        }
#pragma unroll
        for (int i = 0; i < 2; i++) {
            int idx = tid + i * 256;
            int row = idx >> 3, c = (idx & 7) * 8;
            const size_t gs = (size_t)row * C + k0 + c;
            const uint32_t d = (uint32_t)(row * ASTR + c) * 2;
            cp16(sb + BH_OFF * 2 + d, Bh + gs);
            cp16(sb + BL_OFF * 2 + d, Bl + gs);
        }
        CP_COMMIT();
    };

    auto compute = [&](int buf) {
        const uint32_t sb = su + (uint32_t)buf * (STG_ELEMS * 2);
#pragma unroll
        for (int kk = 0; kk < 64; kk += 16) {
            uint32_t ah[2][4], al[2][4], bh[8], bl[8];
#pragma unroll
            for (int mi = 0; mi < 2; mi++) {
                uint32_t base = sb + (uint32_t)((wm * 32 + mi * 16) * ASTR + kk) * 2 + aoff;
                ldsm4(ah[mi], base + AH_OFF * 2);
                ldsm4(al[mi], base + AL_OFF * 2);
            }
#pragma unroll
            for (int n2 = 0; n2 < 2; n2++) {
                uint32_t base = sb + (uint32_t)((wn * 32 + n2 * 16) * ASTR + kk) * 2 + boff;
                ldsm4(bh + n2 * 4, base + BH_OFF * 2);
                ldsm4(bl + n2 * 4, base + BL_OFF * 2);
            }
#pragma unroll
            for (int mi = 0; mi < 2; mi++)
#pragma unroll
                for (int nf = 0; nf < 4; nf++) {
                    float* d = acc[mi][nf];
                    mma_bf16(d, ah[mi], bh + nf * 2);   // hi*hi
                    mma_bf16(d, ah[mi], bl + nf * 2);   // hi*lo
                    mma_bf16(d, al[mi], bh + nf * 2);   // lo*hi
                }
        }
    };

    load_stage(0, 0);
    load_stage(1, 64);

    for (int j = 0; j < 16; j++) {
        if (j < 14) CP_WAIT1(); else CP_WAIT0();
        __syncthreads();
        compute(j & 1);
        if (j + 2 < 16) {
            __syncthreads();
            load_stage(j & 1, (j + 2) * 64);
        }
    }

    // epilogue: split fp32 acc to bf16 hi/lo and store
    const int g2 = lane >> 2;
    const int t2 = (lane & 3) * 2;
    if (w < 2) {
        __nv_bfloat16* dh = w ? g_kh : g_qh;
        __nv_bfloat16* dl = w ? g_kl : g_ql;
        const float sc = w ? 1.0f : QSCALE;
#pragma unroll
        for (int mi = 0; mi < 2; mi++)
#pragma unroll
            for (int nf = 0; nf < 4; nf++) {
                const size_t row0 = rowBase + wm * 32 + mi * 16 + g2;
                const int col = wn * 32 + nf * 8 + t2;
                __nv_bfloat16 h[4], l[4];
#pragma unroll
                for (int u = 0; u < 4; u++) split1(acc[mi][nf][u] * sc, h[u], l[u]);
                *(__nv_bfloat162*)(dh + row0 * H + col)       = {h[0], h[1]};
                *(__nv_bfloat162*)(dl + row0 * H + col)       = {l[0], l[1]};
                *(__nv_bfloat162*)(dh + (row0 + 8) * H + col) = {h[2], h[3]};
                *(__nv_bfloat162*)(dl + (row0 + 8) * H + col) = {l[2], l[3]};
            }
    } else {
        // V: store transposed Vt[h][row]
#pragma unroll
        for (int mi = 0; mi < 2; mi++)
#pragma unroll
            for (int nf = 0; nf < 4; nf++) {
                const size_t row0 = rowBase + wm * 32 + mi * 16 + g2;
                const int col = wn * 32 + nf * 8 + t2;
                __nv_bfloat16 h[4], l[4];
#pragma unroll
                for (int u = 0; u < 4; u++) split1(acc[mi][nf][u], h[u], l[u]);
                g_vth[(size_t)col * NROW + row0]           = h[0];
                g_vth[(size_t)(col + 1) * NROW + row0]     = h[1];
                g_vth[(size_t)col * NROW + row0 + 8]       = h[2];
                g_vth[(size_t)(col + 1) * NROW + row0 + 8] = h[3];
                g_vtl[(size_t)col * NROW + row0]           = l[0];
                g_vtl[(size_t)(col + 1) * NROW + row0]     = l[1];
                g_vtl[(size_t)col * NROW + row0 + 8]       = l[2];
                g_vtl[(size_t)(col + 1) * NROW + row0 + 8] = l[3];
            }
    }
}

// ---------------------------------------------------------------------------
// Kernel 2: causal flash attention on HMMA.
// grid = (32 q-tiles of 64, B), 128 threads = 4 warps; warp owns 16 q-rows.
// S = Q K^T (3-split MMA), online softmax on register c-frags, P repacked
// in-register to A-frags (hi/lo split), O += P Vt^T (3-split MMA).
// ---------------------------------------------------------------------------
#define AT_STR 72
#define QH_E 0
#define QL_E 4608
#define STG_E(b) (9216 + (b) * 18432)
#define KH_E 0
#define KL_E 4608
#define VH_E 9216
#define VL_E 13824
#define ATT_SMEM (46080 * 2)   // 92160 bytes

__global__ __launch_bounds__(128, 2) void attn_mma(float* __restrict__ out) {
    extern __shared__ __nv_bfloat16 smb[];
    const uint32_t su = smem_u32(smb);
    const int tid = threadIdx.x;
    const int lane = tid & 31;
    const int wid = tid >> 5;          // warp = m block (16 rows)
    const int bT = blockIdx.y * T;
    const int qt = blockIdx.x;
    const int qBase = qt * 64;

    const int g2 = lane >> 2;
    const int t2 = (lane & 3) * 2;
    const uint32_t aoff = (uint32_t)((lane & 15) * AT_STR + ((lane >> 4) << 3)) * 2;
    const uint32_t boff = (uint32_t)(((lane & 7) + ((lane >> 4) << 3)) * AT_STR +
                                     (((lane >> 3) & 1) << 3)) * 2;

    auto load_q = [&]() {
#pragma unroll
        for (int i = 0; i < 4; i++) {
            int idx = tid + i * 128;
            int row = idx >> 3, c = (idx & 7) * 8;
            const size_t gs = (size_t)(bT + qBase + row) * H + c;
            const uint32_t d = (uint32_t)(row * AT_STR + c) * 2;
            cp16(su + QH_E * 2 + d, g_qh + gs);
            cp16(su + QL_E * 2 + d, g_ql + gs);
        }
    };
    auto load_kv = [&](int buf, int j) {
        const uint32_t sb = su + STG_E(buf) * 2;
        const int kb = j * 64;
#pragma unroll
        for (int i = 0; i < 4; i++) {
            int idx = tid + i * 128;
            int row = idx >> 3, c = (idx & 7) * 8;
            const uint32_t d = (uint32_t)(row * AT_STR + c) * 2;
            const size_t gk = (size_t)(bT + kb + row) * H + c;
            cp16(sb + KH_E * 2 + d, g_kh + gk);
            cp16(sb + KL_E * 2 + d, g_kl + gk);
            const size_t gv = (size_t)row * NROW + bT + kb + c;   // row = h
            cp16(sb + VH_E * 2 + d, g_vth + gv);
            cp16(sb + VL_E * 2 + d, g_vtl + gv);
        }
        CP_COMMIT();
    };

    load_q();
    load_kv(0, 0);
    CP_COMMIT();
    if (qt >= 1) load_kv(1, 1);

    uint32_t qfh[4][4], qfl[4][4];
    float o[8][4] = {};
    float m0 = -1e30f, m1 = -1e30f, l0 = 0.0f, l1 = 0.0f;
    const int r0loc = 16 * wid + g2;

    for (int j = 0; j <= qt; j++) {
        if (j < qt) CP_WAIT1(); else CP_WAIT0();
        __syncthreads();

        if (j == 0) {
#pragma unroll
            for (int kf = 0; kf < 4; kf++) {
                const uint32_t base =
                    (uint32_t)((16 * wid) * AT_STR + kf * 16) * 2 + aoff;
                ldsm4(qfh[kf], su + QH_E * 2 + base);
                ldsm4(qfl[kf], su + QL_E * 2 + base);
            }
        }

        const uint32_t sb = su + STG_E(j & 1) * 2;

        // ---- S = Q K^T ----
        float sa[8][4] = {};
#pragma unroll
        for (int kf = 0; kf < 4; kf++) {
            uint32_t bh[16], bl[16];
#pragma unroll
            for (int n2 = 0; n2 < 4; n2++) {
                const uint32_t base =
                    (uint32_t)((n2 * 16) * AT_STR + kf * 16) * 2 + boff;
                ldsm4(bh + n2 * 4, sb + KH_E * 2 + base);
                ldsm4(bl + n2 * 4, sb + KL_E * 2 + base);
            }
#pragma unroll
            for (int nf = 0; nf < 8; nf++) {
                mma_bf16(sa[nf], qfh[kf], bh + nf * 2);
                mma_bf16(sa[nf], qfh[kf], bl + nf * 2);
                mma_bf16(sa[nf], qfl[kf], bh + nf * 2);
            }
        }

        // ---- causal mask (diag tile only; kBase == qBase) ----
        if (j == qt) {
#pragma unroll
            for (int nf = 0; nf < 8; nf++) {
                const int n0 = nf * 8 + t2;
                if (n0     > r0loc)     sa[nf][0] = -1e30f;
                if (n0 + 1 > r0loc)     sa[nf][1] = -1e30f;
                if (n0     > r0loc + 8) sa[nf][2] = -1e30f;
                if (n0 + 1 > r0loc + 8) sa[nf][3] = -1e30f;
            }
        }

        // ---- online softmax (log2 domain; QSCALE folded into Q) ----
        float mx0 = -1e30f, mx1 = -1e30f;
#pragma unroll
        for (int nf = 0; nf < 8; nf++) {
            mx0 = fmaxf(mx0, fmaxf(sa[nf][0], sa[nf][1]));
            mx1 = fmaxf(mx1, fmaxf(sa[nf][2], sa[nf][3]));
        }
        mx0 = fmaxf(mx0, __shfl_xor_sync(0xffffffffu, mx0, 1));
        mx0 = fmaxf(mx0, __shfl_xor_sync(0xffffffffu, mx0, 2));
        mx1 = fmaxf(mx1, __shfl_xor_sync(0xffffffffu, mx1, 1));
        mx1 = fmaxf(mx1, __shfl_xor_sync(0xffffffffu, mx1, 2));
        const float mn0 = fmaxf(m0, mx0);
        const float mn1 = fmaxf(m1, mx1);
        const float corr0 = exp2f(m0 - mn0);
        const float corr1 = exp2f(m1 - mn1);

        uint32_t pah[4][4], pal[4][4];
        float rs0 = 0.0f, rs1 = 0.0f;
#pragma unroll
        for (int nf = 0; nf < 8; nf++) {
            const float p0 = exp2f(sa[nf][0] - mn0);
            const float p1 = exp2f(sa[nf][1] - mn0);
            const float p2 = exp2f(sa[nf][2] - mn1);
            const float p3 = exp2f(sa[nf][3] - mn1);
            rs0 += p0 + p1;
            rs1 += p2 + p3;
            __nv_bfloat16 h0, h1, h2, h3, lo0, lo1, lo2, lo3;
            split1(p0, h0, lo0); split1(p1, h1, lo1);
            split1(p2, h2, lo2); split1(p3, h3, lo3);
            const int kf = nf >> 1;
            const int rb = (nf & 1) * 2;
            pah[kf][rb]     = bf2pack(h0, h1);
            pah[kf][rb + 1] = bf2pack(h2, h3);
            pal[kf][rb]     = bf2pack(lo0, lo1);
            pal[kf][rb + 1] = bf2pack(lo2, lo3);
        }
        rs0 += __shfl_xor_sync(0xffffffffu, rs0, 1);
        rs0 += __shfl_xor_sync(0xffffffffu, rs0, 2);
        rs1 += __shfl_xor_sync(0xffffffffu, rs1, 1);
        rs1 += __shfl_xor_sync(0xffffffffu, rs1, 2);
        l0 = l0 * corr0 + rs0;
        l1 = l1 * corr1 + rs1;
        m0 = mn0;
        m1 = mn1;
#pragma unroll
        for (int hf = 0; hf < 8; hf++) {
            o[hf][0] *= corr0; o[hf][1] *= corr0;
            o[hf][2] *= corr1; o[hf][3] *= corr1;
        }

        // ---- O += P Vt^T ----
#pragma unroll
        for (int kf = 0; kf < 4; kf++) {
            uint32_t vh[16], vl[16];
#pragma unroll
            for (int n2 = 0; n2 < 4; n2++) {
                const uint32_t base =
                    (uint32_t)((n2 * 16) * AT_STR + kf * 16) * 2 + boff;
                ldsm4(vh + n2 * 4, sb + VH_E * 2 + base);
                ldsm4(vl + n2 * 4, sb + VL_E * 2 + base);
            }
#pragma unroll
            for (int hf = 0; hf < 8; hf++) {
                mma_bf16(o[hf], pah[kf], vh + hf * 2);
                mma_bf16(o[hf], pah[kf], vl + hf * 2);
                mma_bf16(o[hf], pal[kf], vh + hf * 2);
            }
        }

        if (j + 2 <= qt) {
            __syncthreads();
            load_kv(j & 1, j + 2);
        }
    }

    // ---- epilogue ----
    const float inv0 = 1.0f / l0;
    const float inv1 = 1.0f / l1;
    const size_t row0 = (size_t)(bT + qBase + 16 * wid + g2);
#pragma unroll
    for (int hf = 0; hf < 8; hf++) {
        const int col = hf * 8 + t2;
        float2 w0 = {o[hf][0] * inv0, o[hf][1] * inv0};
        float2 w1 = {o[hf][2] * inv1, o[hf][3] * inv1};
        *(float2*)(out + row0 * H + col)       = w0;
        *(float2*)(out + (row0 + 8) * H + col) = w1;
    }
}

extern "C" void kernel_launch(void* const* d_in, const int* in_sizes, int n_in,
                              void* d_out, int out_size) {
    const float* x  = (const float*)d_in[0];
    const float* Wq = (const float*)d_in[1];
    const float* Wk = (const float*)d_in[2];
    const float* Wv = (const float*)d_in[3];
    float* out = (float*)d_out;

    cudaFuncSetAttribute(qkv_mma, cudaFuncAttributeMaxDynamicSharedMemorySize,
                         PROJ_SMEM);
    cudaFuncSetAttribute(attn_mma, cudaFuncAttributeMaxDynamicSharedMemorySize,
                         ATT_SMEM);

    convert_split<<<(X4 + W4 + 255) / 256, 256>>>(x, Wq, Wk, Wv);
    qkv_mma<<<dim3(64, 3), 256, PROJ_SMEM>>>();
    attn_mma<<<dim3(32, B), 128, ATT_SMEM>>>(out);
}

// round 8
// speedup vs baseline: 5.2341x; 1.4713x over previous
#include <cuda_runtime.h>
#include <cuda_bf16.h>
#include <cstdint>
#include <cstddef>

#define B 4
#define T 2048
#define C 1024
#define H 64
#define NROW (B * T)
#define QSCALE 0.18033688011112042f   // 0.125 * log2(e)

// pre-split W (hi/lo bf16): rows 0-63 Wq, 64-127 Wk, 128-191 Wv
__device__ __align__(16) __nv_bfloat16 g_wh[192 * C];
__device__ __align__(16) __nv_bfloat16 g_wl[192 * C];
// projected q/k (bf16 hi/lo, [row][h]; q pre-scaled) and transposed v ([h][row])
__device__ __align__(16) __nv_bfloat16 g_qh[NROW * H];
__device__ __align__(16) __nv_bfloat16 g_ql[NROW * H];
__device__ __align__(16) __nv_bfloat16 g_kh[NROW * H];
__device__ __align__(16) __nv_bfloat16 g_kl[NROW * H];
__device__ __align__(16) __nv_bfloat16 g_vth[H * NROW];
__device__ __align__(16) __nv_bfloat16 g_vtl[H * NROW];
// split-K attention partials: [split][row][...]
__device__ float g_po[2 * NROW * H];
__device__ float g_pm[2 * NROW];
__device__ float g_pl[2 * NROW];

// ---------------------------------------------------------------------------
// Baseline-PTX helpers (sm_80+ only — no tcgen05 on this toolchain)
// ---------------------------------------------------------------------------
__device__ __forceinline__ uint32_t smem_u32(const void* p) {
    uint32_t a;
    asm("{ .reg .u64 t; cvta.to.shared.u64 t, %1; cvt.u32.u64 %0, t; }"
        : "=r"(a) : "l"(p));
    return a;
}
__device__ __forceinline__ void cp16(uint32_t dst, const void* src) {
    asm volatile("cp.async.cg.shared.global [%0], [%1], 16;"
                 :: "r"(dst), "l"(src) : "memory");
}
#define CP_COMMIT() asm volatile("cp.async.commit_group;" ::: "memory")
#define CP_WAIT1()  asm volatile("cp.async.wait_group 1;" ::: "memory")
#define CP_WAIT0()  asm volatile("cp.async.wait_group 0;" ::: "memory")
__device__ __forceinline__ void ldsm4(uint32_t* r, uint32_t addr) {
    asm volatile("ldmatrix.sync.aligned.m8n8.x4.shared.b16 {%0,%1,%2,%3}, [%4];"
                 : "=r"(r[0]), "=r"(r[1]), "=r"(r[2]), "=r"(r[3]) : "r"(addr));
}
__device__ __forceinline__ void mma_bf16(float* d, const uint32_t* a,
                                         const uint32_t* b) {
    asm volatile(
        "mma.sync.aligned.m16n8k16.row.col.f32.bf16.bf16.f32 "
        "{%0,%1,%2,%3}, {%4,%5,%6,%7}, {%8,%9}, {%0,%1,%2,%3};"
        : "+f"(d[0]), "+f"(d[1]), "+f"(d[2]), "+f"(d[3])
        : "r"(a[0]), "r"(a[1]), "r"(a[2]), "r"(a[3]), "r"(b[0]), "r"(b[1]));
}
__device__ __forceinline__ void split1(float v, __nv_bfloat16& h, __nv_bfloat16& l) {
    h = __float2bfloat16(v);
    l = __float2bfloat16(v - __bfloat162float(h));
}
__device__ __forceinline__ uint32_t bf2pack(__nv_bfloat16 lo, __nv_bfloat16 hi) {
    __nv_bfloat162 t{lo, hi};
    return *reinterpret_cast<uint32_t*>(&t);
}

// ---------------------------------------------------------------------------
// Kernel 0: split packed W into bf16 hi/lo (x is split inline in qkv_mma now)
// ---------------------------------------------------------------------------
#define W4 (192 * C / 4)

__global__ __launch_bounds__(256) void convert_w(const float* __restrict__ Wq,
                                                 const float* __restrict__ Wk,
                                                 const float* __restrict__ Wv) {
    int i = blockIdx.x * 256 + threadIdx.x;
    if (i >= W4) return;
    int wrow = i >> 8;            // 0..191
    int c4 = i & 255;
    const float* src = (wrow < 64)  ? Wq + (size_t)wrow * C
                     : (wrow < 128) ? Wk + (size_t)(wrow - 64) * C
                                    : Wv + (size_t)(wrow - 128) * C;
    float4 v = ((const float4*)src)[c4];
    const float a[4] = {v.x, v.y, v.z, v.w};
    __nv_bfloat16 h[4], l[4];
#pragma unroll
    for (int j = 0; j < 4; j++) split1(a[j], h[j], l[j]);
    size_t off = (size_t)wrow * C + (size_t)c4 * 4;
    __nv_bfloat162* ph = (__nv_bfloat162*)(g_wh + off);
    __nv_bfloat162* pl = (__nv_bfloat162*)(g_wl + off);
    ph[0] = {h[0], h[1]}; ph[1] = {h[2], h[3]};
    pl[0] = {l[0], l[1]}; pl[1] = {l[2], l[3]};
}

// ---------------------------------------------------------------------------
// Kernel 1: QKV projection on HMMA, fused x split.
// grid = 128 CTAs (M-tiles of 64 rows), N=192 (q|k|v), 256 threads = 8 warps
// (4m x 2n; warp tile m16 x n96). K chunks of 64, double-buffered:
// x fp32 via LDG -> in-register hi/lo split -> STS; W hi/lo via cp.async.
// ---------------------------------------------------------------------------
#define ASTR 72
#define AH_E 0
#define AL_E 4608          // 64*72
#define BH_E 9216
#define BL_E 23040         // +192*72
#define STG 36864          // bf16 elems per stage
#define PROJ_SMEM (2 * STG * 2)   // 147456 bytes

__global__ __launch_bounds__(256, 1) void qkv_mma(const float* __restrict__ x) {
    extern __shared__ __nv_bfloat16 smb[];
    char* sc = (char*)smb;
    const uint32_t su = smem_u32(smb);
    const int tid = threadIdx.x;
    const int lane = tid & 31;
    const int wid = tid >> 5;
    const int wm = wid & 3;        // m block: rows wm*16..wm*16+15
    const int wn = wid >> 2;       // n block: cols wn*96..wn*96+95
    const int rowBase = blockIdx.x * 64;

    const uint32_t aoff = (uint32_t)((lane & 15) * ASTR + ((lane >> 4) << 3)) * 2;
    const uint32_t boff = (uint32_t)(((lane & 7) + ((lane >> 4) << 3)) * ASTR +
                                     (((lane >> 3) & 1) << 3)) * 2;

    float acc[12][4] = {};
    float4 xr[4];

    auto ldx = [&](float4* r, int chunk) {
#pragma unroll
        for (int i = 0; i < 4; i++) {
            int idx = tid + i * 256;
            int row = idx >> 4, c = (idx & 15) * 4;
            r[i] = *(const float4*)(x + (size_t)(rowBase + row) * C + chunk * 64 + c);
        }
    };
    auto stx = [&](const float4* r, int buf) {
        char* st = sc + buf * (STG * 2);
#pragma unroll
        for (int i = 0; i < 4; i++) {
            int idx = tid + i * 256;
            int row = idx >> 4, c = (idx & 15) * 4;
            const float a[4] = {r[i].x, r[i].y, r[i].z, r[i].w};
            __nv_bfloat16 h[4], l[4];
#pragma unroll
            for (int u = 0; u < 4; u++) split1(a[u], h[u], l[u]);
            const uint32_t d = (uint32_t)(row * ASTR + c) * 2;
            *(uint32_t*)(st + AH_E * 2 + d)     = bf2pack(h[0], h[1]);
            *(uint32_t*)(st + AH_E * 2 + d + 4) = bf2pack(h[2], h[3]);
            *(uint32_t*)(st + AL_E * 2 + d)     = bf2pack(l[0], l[1]);
            *(uint32_t*)(st + AL_E * 2 + d + 4) = bf2pack(l[2], l[3]);
        }
    };
    auto ldw = [&](int buf, int chunk) {
        const uint32_t sb = su + (uint32_t)buf * (STG * 2);
        const int k0 = chunk * 64;
#pragma unroll
        for (int i = 0; i < 6; i++) {
            int idx = tid + i * 256;
            int row = idx >> 3, c = (idx & 7) * 8;   // 192 rows x 8 cp16
            const size_t gs = (size_t)row * C + k0 + c;
            const uint32_t d = (uint32_t)(row * ASTR + c) * 2;
            cp16(sb + BH_E * 2 + d, g_wh + gs);
            cp16(sb + BL_E * 2 + d, g_wl + gs);
        }
        CP_COMMIT();
    };
    auto compute = [&](int buf) {
        const uint32_t sb = su + (uint32_t)buf * (STG * 2);
#pragma unroll
        for (int kf = 0; kf < 4; kf++) {
            uint32_t ah[4], al[4];
            const uint32_t abase =
                sb + (uint32_t)((wm * 16) * ASTR + kf * 16) * 2 + aoff;
            ldsm4(ah, abase + AH_E * 2);
            ldsm4(al, abase + AL_E * 2);
#pragma unroll
            for (int n2 = 0; n2 < 6; n2++) {
                uint32_t bh[4], bl[4];
                const uint32_t bbase =
                    sb + (uint32_t)((wn * 96 + n2 * 16) * ASTR + kf * 16) * 2 + boff;
                ldsm4(bh, bbase + BH_E * 2);
                ldsm4(bl, bbase + BL_E * 2);
#pragma unroll
                for (int h2 = 0; h2 < 2; h2++) {
                    float* d = acc[n2 * 2 + h2];
                    mma_bf16(d, ah, bh + h2 * 2);   // hi*hi
                    mma_bf16(d, ah, bl + h2 * 2);   // hi*lo
                    mma_bf16(d, al, bh + h2 * 2);   // lo*hi
                }
            }
        }
    };

    // prologue: chunks 0,1
    ldx(xr, 0); stx(xr, 0);
    ldx(xr, 1); stx(xr, 1);
    ldw(0, 0);
    ldw(1, 1);

    for (int j = 0; j < 16; j++) {
        if (j + 2 < 16) ldx(xr, j + 2);          // LDG early, hidden under MMA
        if (j < 14) CP_WAIT1(); else CP_WAIT0();
        __syncthreads();
        compute(j & 1);
        __syncthreads();
        if (j + 2 < 16) { stx(xr, j & 1); ldw(j & 1, j + 2); }
    }

    // epilogue: split fp32 acc to bf16 hi/lo; route per weight (col/64)
    const int g2 = lane >> 2;
    const int t2 = (lane & 3) * 2;
#pragma unroll
    for (int nf = 0; nf < 12; nf++) {
        const int colg = wn * 96 + nf * 8 + t2;
        const int w = colg >> 6;
        const int c = colg & 63;
        const size_t row0 = rowBase + wm * 16 + g2;
        __nv_bfloat16 h[4], l[4];
        if (w < 2) {
            __nv_bfloat16* dh = w ? g_kh : g_qh;
            __nv_bfloat16* dl = w ? g_kl : g_ql;
            const float s = w ? 1.0f : QSCALE;
#pragma unroll
            for (int u = 0; u < 4; u++) split1(acc[nf][u] * s, h[u], l[u]);
            *(__nv_bfloat162*)(dh + row0 * H + c)       = {h[0], h[1]};
            *(__nv_bfloat162*)(dl + row0 * H + c)       = {l[0], l[1]};
            *(__nv_bfloat162*)(dh + (row0 + 8) * H + c) = {h[2], h[3]};
            *(__nv_bfloat162*)(dl + (row0 + 8) * H + c) = {l[2], l[3]};
        } else {
#pragma unroll
            for (int u = 0; u < 4; u++) split1(acc[nf][u], h[u], l[u]);
            g_vth[(size_t)c * NROW + row0]           = h[0];
            g_vth[(size_t)(c + 1) * NROW + row0]     = h[1];
            g_vth[(size_t)c * NROW + row0 + 8]       = h[2];
            g_vth[(size_t)(c + 1) * NROW + row0 + 8] = h[3];
            g_vtl[(size_t)c * NROW + row0]           = l[0];
            g_vtl[(size_t)(c + 1) * NROW + row0]     = l[1];
            g_vtl[(size_t)c * NROW + row0 + 8]       = l[2];
            g_vtl[(size_t)(c + 1) * NROW + row0 + 8] = l[3];
        }
    }
}

// ---------------------------------------------------------------------------
// Kernel 2: causal flash attention on HMMA, split-K over the key range.
// grid = 256 CTAs (32 q-tiles x 2 splits x 4 batches), decoded longest-first
// with a fold so bid%148 SM placement pairs long CTAs with short ones.
// Each CTA writes unnormalized partials (o_raw, m, l); combine() merges.
// ---------------------------------------------------------------------------
#define AT_STR 72
#define QH_E 0
#define QL_E 4608
#define STG_E(b) (9216 + (b) * 18432)
#define KH_E 0
#define KL_E 4608
#define VH_E 9216
#define VL_E 13824
#define ATT_SMEM (46080 * 2)   // 92160 bytes

__global__ __launch_bounds__(128, 2) void attn_mma() {
    extern __shared__ __nv_bfloat16 smb[];
    const uint32_t su = smem_u32(smb);
    const int tid = threadIdx.x;
    const int lane = tid & 31;
    const int wid = tid >> 5;

    // job decode: global longest-first; fold second wave short-end-first
    const int idx = blockIdx.x;
    const int job = (idx < 148) ? idx : (403 - idx);
    const int qt  = 31 - (job >> 3);
    const int sub = job & 7;
    const int s   = sub & 1;
    const int bT  = (sub >> 1) * T;
    const int qBase = qt * 64;

    const int n_tiles = qt + 1;
    const int h1 = (n_tiles + 1) >> 1;
    const int start = s ? h1 : 0;
    const int end   = s ? n_tiles : h1;

    if (start >= end) {   // empty split (qt==0, s==1): write identity partial
        for (int i = tid; i < 64 * 16; i += 128) {
            int row = i >> 4, c4 = i & 15;
            *(float4*)(g_po + ((size_t)s * NROW + bT + qBase + row) * H + c4 * 4) =
                make_float4(0.f, 0.f, 0.f, 0.f);
        }
        if (tid < 64) {
            size_t pr = (size_t)s * NROW + bT + qBase + tid;
            g_pm[pr] = -1e30f;
            g_pl[pr] = 0.f;
        }
        return;
    }

    const int g2 = lane >> 2;
    const int t2 = (lane & 3) * 2;
    const uint32_t aoff = (uint32_t)((lane & 15) * AT_STR + ((lane >> 4) << 3)) * 2;
    const uint32_t boff = (uint32_t)(((lane & 7) + ((lane >> 4) << 3)) * AT_STR +
                                     (((lane >> 3) & 1) << 3)) * 2;

    auto load_q = [&]() {
#pragma unroll
        for (int i = 0; i < 4; i++) {
            int idx2 = tid + i * 128;
            int row = idx2 >> 3, c = (idx2 & 7) * 8;
            const size_t gs = (size_t)(bT + qBase + row) * H + c;
            const uint32_t d = (uint32_t)(row * AT_STR + c) * 2;
            cp16(su + QH_E * 2 + d, g_qh + gs);
            cp16(su + QL_E * 2 + d, g_ql + gs);
        }
    };
    auto load_kv = [&](int buf, int j) {
        const uint32_t sb = su + STG_E(buf) * 2;
        const int kb = j * 64;
#pragma unroll
        for (int i = 0; i < 4; i++) {
            int idx2 = tid + i * 128;
            int row = idx2 >> 3, c = (idx2 & 7) * 8;
            const uint32_t d = (uint32_t)(row * AT_STR + c) * 2;
            const size_t gk = (size_t)(bT + kb + row) * H + c;
            cp16(sb + KH_E * 2 + d, g_kh + gk);
            cp16(sb + KL_E * 2 + d, g_kl + gk);
            const size_t gv = (size_t)row * NROW + bT + kb + c;   // row = h
            cp16(sb + VH_E * 2 + d, g_vth + gv);
            cp16(sb + VL_E * 2 + d, g_vtl + gv);
        }
        CP_COMMIT();
    };

    load_q();
    load_kv(0, start);
    CP_COMMIT();
    if (start + 1 < end) load_kv(1, start + 1);

    uint32_t qfh[4][4], qfl[4][4];
    float o[8][4] = {};
    float m0 = -1e30f, m1 = -1e30f, l0 = 0.0f, l1 = 0.0f;
    const int r0loc = 16 * wid + g2;

    for (int j = start; j < end; j++) {
        if (j < end - 1) CP_WAIT1(); else CP_WAIT0();
        __syncthreads();

        if (j == start) {
#pragma unroll
            for (int kf = 0; kf < 4; kf++) {
                const uint32_t base =
                    (uint32_t)((16 * wid) * AT_STR + kf * 16) * 2 + aoff;
                ldsm4(qfh[kf], su + QH_E * 2 + base);
                ldsm4(qfl[kf], su + QL_E * 2 + base);
            }
        }

        const uint32_t sb = su + STG_E((j - start) & 1) * 2;

        // ---- S = Q K^T ----
        float sa[8][4] = {};
#pragma unroll
        for (int kf = 0; kf < 4; kf++) {
            uint32_t bh[16], bl[16];
#pragma unroll
            for (int n2 = 0; n2 < 4; n2++) {
                const uint32_t base =
                    (uint32_t)((n2 * 16) * AT_STR + kf * 16) * 2 + boff;
                ldsm4(bh + n2 * 4, sb + KH_E * 2 + base);
                ldsm4(bl + n2 * 4, sb + KL_E * 2 + base);
            }
#pragma unroll
            for (int nf = 0; nf < 8; nf++) {
                mma_bf16(sa[nf], qfh[kf], bh + nf * 2);
                mma_bf16(sa[nf], qfh[kf], bl + nf * 2);
                mma_bf16(sa[nf], qfl[kf], bh + nf * 2);
            }
        }

        // ---- causal mask (diag tile only; kBase == qBase there) ----
        if (j == qt) {
#pragma unroll
            for (int nf = 0; nf < 8; nf++) {
                const int n0 = nf * 8 + t2;
                if (n0     > r0loc)     sa[nf][0] = -1e30f;
                if (n0 + 1 > r0loc)     sa[nf][1] = -1e30f;
                if (n0     > r0loc + 8) sa[nf][2] = -1e30f;
                if (n0 + 1 > r0loc + 8) sa[nf][3] = -1e30f;
            }
        }

        // ---- online softmax (log2 domain; QSCALE folded into Q) ----
        float mx0 = -1e30f, mx1 = -1e30f;
#pragma unroll
        for (int nf = 0; nf < 8; nf++) {
            mx0 = fmaxf(mx0, fmaxf(sa[nf][0], sa[nf][1]));
            mx1 = fmaxf(mx1, fmaxf(sa[nf][2], sa[nf][3]));
        }
        mx0 = fmaxf(mx0, __shfl_xor_sync(0xffffffffu, mx0, 1));
        mx0 = fmaxf(mx0, __shfl_xor_sync(0xffffffffu, mx0, 2));
        mx1 = fmaxf(mx1, __shfl_xor_sync(0xffffffffu, mx1, 1));
        mx1 = fmaxf(mx1, __shfl_xor_sync(0xffffffffu, mx1, 2));
        const float mn0 = fmaxf(m0, mx0);
        const float mn1 = fmaxf(m1, mx1);
        const float corr0 = exp2f(m0 - mn0);
        const float corr1 = exp2f(m1 - mn1);

        uint32_t pah[4][4], pal[4][4];
        float rs0 = 0.0f, rs1 = 0.0f;
#pragma unroll
        for (int nf = 0; nf < 8; nf++) {
            const float p0 = exp2f(sa[nf][0] - mn0);
            const float p1 = exp2f(sa[nf][1] - mn0);
            const float p2 = exp2f(sa[nf][2] - mn1);
            const float p3 = exp2f(sa[nf][3] - mn1);
            rs0 += p0 + p1;
            rs1 += p2 + p3;
            __nv_bfloat16 h0, h1, h2, h3, lo0, lo1, lo2, lo3;
            split1(p0, h0, lo0); split1(p1, h1, lo1);
            split1(p2, h2, lo2); split1(p3, h3, lo3);
            const int kf = nf >> 1;
            const int rb = (nf & 1) * 2;
            pah[kf][rb]     = bf2pack(h0, h1);
            pah[kf][rb + 1] = bf2pack(h2, h3);
            pal[kf][rb]     = bf2pack(lo0, lo1);
            pal[kf][rb + 1] = bf2pack(lo2, lo3);
        }
        rs0 += __shfl_xor_sync(0xffffffffu, rs0, 1);
        rs0 += __shfl_xor_sync(0xffffffffu, rs0, 2);
        rs1 += __shfl_xor_sync(0xffffffffu, rs1, 1);
        rs1 += __shfl_xor_sync(0xffffffffu, rs1, 2);
        l0 = l0 * corr0 + rs0;
        l1 = l1 * corr1 + rs1;
        m0 = mn0;
        m1 = mn1;
#pragma unroll
        for (int hf = 0; hf < 8; hf++) {
            o[hf][0] *= corr0; o[hf][1] *= corr0;
            o[hf][2] *= corr1; o[hf][3] *= corr1;
        }

        // ---- O += P Vt^T ----
#pragma unroll
        for (int kf = 0; kf < 4; kf++) {
            uint32_t vh[16], vl[16];
#pragma unroll
            for (int n2 = 0; n2 < 4; n2++) {
                const uint32_t base =
                    (uint32_t)((n2 * 16) * AT_STR + kf * 16) * 2 + boff;
                ldsm4(vh + n2 * 4, sb + VH_E * 2 + base);
                ldsm4(vl + n2 * 4, sb + VL_E * 2 + base);
            }
#pragma unroll
            for (int hf = 0; hf < 8; hf++) {
                mma_bf16(o[hf], pah[kf], vh + hf * 2);
                mma_bf16(o[hf], pah[kf], vl + hf * 2);
                mma_bf16(o[hf], pal[kf], vh + hf * 2);
            }
        }

        if (j + 2 < end) {
            __syncthreads();
            load_kv((j - start) & 1, j + 2);
        }
    }

    // ---- epilogue: unnormalized partials + stats ----
    const size_t row0 = (size_t)s * NROW + bT + qBase + 16 * wid + g2;
#pragma unroll
    for (int hf = 0; hf < 8; hf++) {
        const int col = hf * 8 + t2;
        *(float2*)(g_po + row0 * H + col)       = {o[hf][0], o[hf][1]};
        *(float2*)(g_po + (row0 + 8) * H + col) = {o[hf][2], o[hf][3]};
    }
    if ((lane & 3) == 0) {
        g_pm[row0]     = m0;  g_pl[row0]     = l0;
        g_pm[row0 + 8] = m1;  g_pl[row0 + 8] = l1;
    }
}

// ---------------------------------------------------------------------------
// Kernel 3: merge the two split-K partials into the final output.
// ---------------------------------------------------------------------------
__global__ __launch_bounds__(256) void combine(float* __restrict__ out) {
    const int idx = blockIdx.x * 256 + threadIdx.x;   // NROW*16 = 131072
    const int row = idx >> 4, c4 = idx & 15;
    const float m0 = g_pm[row], m1 = g_pm[NROW + row];
    const float l0 = g_pl[row], l1 = g_pl[NROW + row];
    const float M = fmaxf(m0, m1);
    float w0 = exp2f(m0 - M), w1 = exp2f(m1 - M);
    const float inv = 1.0f / (l0 * w0 + l1 * w1);
    w0 *= inv; w1 *= inv;
    const float4 a = *(const float4*)(g_po + (size_t)row * H + c4 * 4);
    const float4 b = *(const float4*)(g_po + (size_t)(NROW + row) * H + c4 * 4);
    float4 o = {a.x * w0 + b.x * w1, a.y * w0 + b.y * w1,
                a.z * w0 + b.z * w1, a.w * w0 + b.w * w1};
    *(float4*)(out + (size_t)row * H + c4 * 4) = o;
}

extern "C" void kernel_launch(void* const* d_in, const int* in_sizes, int n_in,
                              void* d_out, int out_size) {
    const float* x  = (const float*)d_in[0];
    const float* Wq = (const float*)d_in[1];
    const float* Wk = (const float*)d_in[2];
    const float* Wv = (const float*)d_in[3];
    float* out = (float*)d_out;

    cudaFuncSetAttribute(qkv_mma, cudaFuncAttributeMaxDynamicSharedMemorySize,
                         PROJ_SMEM);
    cudaFuncSetAttribute(attn_mma, cudaFuncAttributeMaxDynamicSharedMemorySize,
                         ATT_SMEM);

    convert_w<<<W4 / 256, 256>>>(Wq, Wk, Wv);
    qkv_mma<<<128, 256, PROJ_SMEM>>>(x);
    attn_mma<<<256, 128, ATT_SMEM>>>();
    combine<<<NROW * 16 / 256, 256>>>(out);
}

// round 9
// speedup vs baseline: 5.2550x; 1.0040x over previous
#include <cuda_runtime.h>
#include <cuda_bf16.h>
#include <cstdint>
#include <cstddef>

#define B 4
#define T 2048
#define C 1024
#define H 64
#define NROW (B * T)
#define QSCALE 0.18033688011112042f   // 0.125 * log2(e)

// pre-split W (hi/lo bf16): rows 0-63 Wq, 64-127 Wk, 128-191 Wv
__device__ __align__(16) __nv_bfloat16 g_wh[192 * C];
__device__ __align__(16) __nv_bfloat16 g_wl[192 * C];
// projected q/k (bf16 hi/lo, [row][h]; q pre-scaled) and transposed v ([h][row])
__device__ __align__(16) __nv_bfloat16 g_qh[NROW * H];
__device__ __align__(16) __nv_bfloat16 g_ql[NROW * H];
__device__ __align__(16) __nv_bfloat16 g_kh[NROW * H];
__device__ __align__(16) __nv_bfloat16 g_kl[NROW * H];
__device__ __align__(16) __nv_bfloat16 g_vth[H * NROW];
__device__ __align__(16) __nv_bfloat16 g_vtl[H * NROW];
// split-K attention partials: [split][row][...]
__device__ float g_po[2 * NROW * H];
__device__ float g_pm[2 * NROW];
__device__ float g_pl[2 * NROW];

// ---------------------------------------------------------------------------
// Baseline-PTX helpers (sm_80+ only — no tcgen05 on this toolchain)
// ---------------------------------------------------------------------------
__device__ __forceinline__ uint32_t smem_u32(const void* p) {
    uint32_t a;
    asm("{ .reg .u64 t; cvta.to.shared.u64 t, %1; cvt.u32.u64 %0, t; }"
        : "=r"(a) : "l"(p));
    return a;
}
__device__ __forceinline__ void cp16(uint32_t dst, const void* src) {
    asm volatile("cp.async.cg.shared.global [%0], [%1], 16;"
                 :: "r"(dst), "l"(src) : "memory");
}
#define CP_COMMIT() asm volatile("cp.async.commit_group;" ::: "memory")
#define CP_WAIT1()  asm volatile("cp.async.wait_group 1;" ::: "memory")
#define CP_WAIT0()  asm volatile("cp.async.wait_group 0;" ::: "memory")
__device__ __forceinline__ void ldsm4(uint32_t* r, uint32_t addr) {
    asm volatile("ldmatrix.sync.aligned.m8n8.x4.shared.b16 {%0,%1,%2,%3}, [%4];"
                 : "=r"(r[0]), "=r"(r[1]), "=r"(r[2]), "=r"(r[3]) : "r"(addr));
}
__device__ __forceinline__ void mma_bf16(float* d, const uint32_t* a,
                                         const uint32_t* b) {
    asm volatile(
        "mma.sync.aligned.m16n8k16.row.col.f32.bf16.bf16.f32 "
        "{%0,%1,%2,%3}, {%4,%5,%6,%7}, {%8,%9}, {%0,%1,%2,%3};"
        : "+f"(d[0]), "+f"(d[1]), "+f"(d[2]), "+f"(d[3])
        : "r"(a[0]), "r"(a[1]), "r"(a[2]), "r"(a[3]), "r"(b[0]), "r"(b[1]));
}
__device__ __forceinline__ void split1(float v, __nv_bfloat16& h, __nv_bfloat16& l) {
    h = __float2bfloat16(v);
    l = __float2bfloat16(v - __bfloat162float(h));
}
__device__ __forceinline__ uint32_t bf2pack(__nv_bfloat16 lo, __nv_bfloat16 hi) {
    __nv_bfloat162 t{lo, hi};
    return *reinterpret_cast<uint32_t*>(&t);
}

// ---------------------------------------------------------------------------
// Kernel 0: split packed W into bf16 hi/lo (x is split inline in qkv_mma now)
// ---------------------------------------------------------------------------
#define W4 (192 * C / 4)

__global__ __launch_bounds__(256) void convert_w(const float* __restrict__ Wq,
                                                 const float* __restrict__ Wk,
                                                 const float* __restrict__ Wv) {
    int i = blockIdx.x * 256 + threadIdx.x;
    if (i >= W4) return;
    int wrow = i >> 8;            // 0..191
    int c4 = i & 255;
    const float* src = (wrow < 64)  ? Wq + (size_t)wrow * C
                     : (wrow < 128) ? Wk + (size_t)(wrow - 64) * C
                                    : Wv + (size_t)(wrow - 128) * C;
    float4 v = ((const float4*)src)[c4];
    const float a[4] = {v.x, v.y, v.z, v.w};
    __nv_bfloat16 h[4], l[4];
#pragma unroll
    for (int j = 0; j < 4; j++) split1(a[j], h[j], l[j]);
    size_t off = (size_t)wrow * C + (size_t)c4 * 4;
    __nv_bfloat162* ph = (__nv_bfloat162*)(g_wh + off);
    __nv_bfloat162* pl = (__nv_bfloat162*)(g_wl + off);
    ph[0] = {h[0], h[1]}; ph[1] = {h[2], h[3]};
    pl[0] = {l[0], l[1]}; pl[1] = {l[2], l[3]};
}

// ---------------------------------------------------------------------------
// Kernel 1: QKV projection on HMMA, fused x split.
// grid = 128 CTAs (M-tiles of 64 rows), N=192 (q|k|v), 256 threads = 8 warps
// (4m x 2n; warp tile m16 x n96). K chunks of 64, double-buffered:
// x fp32 via LDG -> in-register hi/lo split -> STS; W hi/lo via cp.async.
// ---------------------------------------------------------------------------
#define ASTR 72
#define AH_E 0
#define AL_E 4608          // 64*72
#define BH_E 9216
#define BL_E 23040         // +192*72
#define STG 36864          // bf16 elems per stage
#define PROJ_SMEM (2 * STG * 2)   // 147456 bytes

__global__ __launch_bounds__(256, 1) void qkv_mma(const float* __restrict__ x) {
    extern __shared__ __nv_bfloat16 smb[];
    char* sc = (char*)smb;
    const uint32_t su = smem_u32(smb);
    const int tid = threadIdx.x;
    const int lane = tid & 31;
    const int wid = tid >> 5;
    const int wm = wid & 3;        // m block: rows wm*16..wm*16+15
    const int wn = wid >> 2;       // n block: cols wn*96..wn*96+95
    const int rowBase = blockIdx.x * 64;

    const uint32_t aoff = (uint32_t)((lane & 15) * ASTR + ((lane >> 4) << 3)) * 2;
    const uint32_t boff = (uint32_t)(((lane & 7) + ((lane >> 4) << 3)) * ASTR +
                                     (((lane >> 3) & 1) << 3)) * 2;

    float acc[12][4] = {};
    float4 xr[4];

    auto ldx = [&](float4* r, int chunk) {
#pragma unroll
        for (int i = 0; i < 4; i++) {
            int idx = tid + i * 256;
            int row = idx >> 4, c = (idx & 15) * 4;
            r[i] = *(const float4*)(x + (size_t)(rowBase + row) * C + chunk * 64 + c);
        }
    };
    auto stx = [&](const float4* r, int buf) {
        char* st = sc + buf * (STG * 2);
#pragma unroll
        for (int i = 0; i < 4; i++) {
            int idx = tid + i * 256;
            int row = idx >> 4, c = (idx & 15) * 4;
            const float a[4] = {r[i].x, r[i].y, r[i].z, r[i].w};
            __nv_bfloat16 h[4], l[4];
#pragma unroll
            for (int u = 0; u < 4; u++) split1(a[u], h[u], l[u]);
            const uint32_t d = (uint32_t)(row * ASTR + c) * 2;
            *(uint32_t*)(st + AH_E * 2 + d)     = bf2pack(h[0], h[1]);
            *(uint32_t*)(st + AH_E * 2 + d + 4) = bf2pack(h[2], h[3]);
            *(uint32_t*)(st + AL_E * 2 + d)     = bf2pack(l[0], l[1]);
            *(uint32_t*)(st + AL_E * 2 + d + 4) = bf2pack(l[2], l[3]);
        }
    };
    auto ldw = [&](int buf, int chunk) {
        const uint32_t sb = su + (uint32_t)buf * (STG * 2);
        const int k0 = chunk * 64;
#pragma unroll
        for (int i = 0; i < 6; i++) {
            int idx = tid + i * 256;
            int row = idx >> 3, c = (idx & 7) * 8;   // 192 rows x 8 cp16
            const size_t gs = (size_t)row * C + k0 + c;
            const uint32_t d = (uint32_t)(row * ASTR + c) * 2;
            cp16(sb + BH_E * 2 + d, g_wh + gs);
            cp16(sb + BL_E * 2 + d, g_wl + gs);
        }
        CP_COMMIT();
    };
    auto compute = [&](int buf) {
        const uint32_t sb = su + (uint32_t)buf * (STG * 2);
#pragma unroll
        for (int kf = 0; kf < 4; kf++) {
            uint32_t ah[4], al[4];
            const uint32_t abase =
                sb + (uint32_t)((wm * 16) * ASTR + kf * 16) * 2 + aoff;
            ldsm4(ah, abase + AH_E * 2);
            ldsm4(al, abase + AL_E * 2);
#pragma unroll
            for (int n2 = 0; n2 < 6; n2++) {
                uint32_t bh[4], bl[4];
                const uint32_t bbase =
                    sb + (uint32_t)((wn * 96 + n2 * 16) * ASTR + kf * 16) * 2 + boff;
                ldsm4(bh, bbase + BH_E * 2);
                ldsm4(bl, bbase + BL_E * 2);
#pragma unroll
                for (int h2 = 0; h2 < 2; h2++) {
                    float* d = acc[n2 * 2 + h2];
                    mma_bf16(d, ah, bh + h2 * 2);   // hi*hi
                    mma_bf16(d, ah, bl + h2 * 2);   // hi*lo
                    mma_bf16(d, al, bh + h2 * 2);   // lo*hi
                }
            }
        }
    };

    // prologue: chunks 0,1
    ldx(xr, 0); stx(xr, 0);
    ldx(xr, 1); stx(xr, 1);
    ldw(0, 0);
    ldw(1, 1);

    for (int j = 0; j < 16; j++) {
        if (j + 2 < 16) ldx(xr, j + 2);          // LDG early, hidden under MMA
        if (j < 14) CP_WAIT1(); else CP_WAIT0();
        __syncthreads();
        compute(j & 1);
        __syncthreads();
        if (j + 2 < 16) { stx(xr, j & 1); ldw(j & 1, j + 2); }
    }

    // epilogue: split fp32 acc to bf16 hi/lo; route per weight (col/64)
    const int g2 = lane >> 2;
    const int t2 = (lane & 3) * 2;
#pragma unroll
    for (int nf = 0; nf < 12; nf++) {
        const int colg = wn * 96 + nf * 8 + t2;
        const int w = colg >> 6;
        const int c = colg & 63;
        const size_t row0 = rowBase + wm * 16 + g2;
        __nv_bfloat16 h[4], l[4];
        if (w < 2) {
            __nv_bfloat16* dh = w ? g_kh : g_qh;
            __nv_bfloat16* dl = w ? g_kl : g_ql;
            const float s = w ? 1.0f : QSCALE;
#pragma unroll
            for (int u = 0; u < 4; u++) split1(acc[nf][u] * s, h[u], l[u]);
            *(__nv_bfloat162*)(dh + row0 * H + c)       = {h[0], h[1]};
            *(__nv_bfloat162*)(dl + row0 * H + c)       = {l[0], l[1]};
            *(__nv_bfloat162*)(dh + (row0 + 8) * H + c) = {h[2], h[3]};
            *(__nv_bfloat162*)(dl + (row0 + 8) * H + c) = {l[2], l[3]};
        } else {
#pragma unroll
            for (int u = 0; u < 4; u++) split1(acc[nf][u], h[u], l[u]);
            g_vth[(size_t)c * NROW + row0]           = h[0];
            g_vth[(size_t)(c + 1) * NROW + row0]     = h[1];
            g_vth[(size_t)c * NROW + row0 + 8]       = h[2];
            g_vth[(size_t)(c + 1) * NROW + row0 + 8] = h[3];
            g_vtl[(size_t)c * NROW + row0]           = l[0];
            g_vtl[(size_t)(c + 1) * NROW + row0]     = l[1];
            g_vtl[(size_t)c * NROW + row0 + 8]       = l[2];
            g_vtl[(size_t)(c + 1) * NROW + row0 + 8] = l[3];
        }
    }
}

// ---------------------------------------------------------------------------
// Kernel 2: causal flash attention on HMMA, split-K over the key range.
// grid = 256 CTAs (32 q-tiles x 2 splits x 4 batches), decoded longest-first
// with a fold so bid%148 SM placement pairs long CTAs with short ones.
// Each CTA writes unnormalized partials (o_raw, m, l); combine() merges.
// ---------------------------------------------------------------------------
#define AT_STR 72
#define QH_E 0
#define QL_E 4608
#define STG_E(b) (9216 + (b) * 18432)
#define KH_E 0
#define KL_E 4608
#define VH_E 9216
#define VL_E 13824
#define ATT_SMEM (46080 * 2)   // 92160 bytes

__global__ __launch_bounds__(128, 2) void attn_mma() {
    extern __shared__ __nv_bfloat16 smb[];
    const uint32_t su = smem_u32(smb);
    const int tid = threadIdx.x;
    const int lane = tid & 31;
    const int wid = tid >> 5;

    // job decode: global longest-first; fold second wave short-end-first
    const int idx = blockIdx.x;
    const int job = (idx < 148) ? idx : (403 - idx);
    const int qt  = 31 - (job >> 3);
    const int sub = job & 7;
    const int s   = sub & 1;
    const int bT  = (sub >> 1) * T;
    const int qBase = qt * 64;

    const int n_tiles = qt + 1;
    const int h1 = (n_tiles + 1) >> 1;
    const int start = s ? h1 : 0;
    const int end   = s ? n_tiles : h1;

    if (start >= end) {   // empty split (qt==0, s==1): write identity partial
        for (int i = tid; i < 64 * 16; i += 128) {
            int row = i >> 4, c4 = i & 15;
            *(float4*)(g_po + ((size_t)s * NROW + bT + qBase + row) * H + c4 * 4) =
                make_float4(0.f, 0.f, 0.f, 0.f);
        }
        if (tid < 64) {
            size_t pr = (size_t)s * NROW + bT + qBase + tid;
            g_pm[pr] = -1e30f;
            g_pl[pr] = 0.f;
        }
        return;
    }

    const int g2 = lane >> 2;
    const int t2 = (lane & 3) * 2;
    const uint32_t aoff = (uint32_t)((lane & 15) * AT_STR + ((lane >> 4) << 3)) * 2;
    const uint32_t boff = (uint32_t)(((lane & 7) + ((lane >> 4) << 3)) * AT_STR +
                                     (((lane >> 3) & 1) << 3)) * 2;

    auto load_q = [&]() {
#pragma unroll
        for (int i = 0; i < 4; i++) {
            int idx2 = tid + i * 128;
            int row = idx2 >> 3, c = (idx2 & 7) * 8;
            const size_t gs = (size_t)(bT + qBase + row) * H + c;
            const uint32_t d = (uint32_t)(row * AT_STR + c) * 2;
            cp16(su + QH_E * 2 + d, g_qh + gs);
            cp16(su + QL_E * 2 + d, g_ql + gs);
        }
    };
    auto load_kv = [&](int buf, int j) {
        const uint32_t sb = su + STG_E(buf) * 2;
        const int kb = j * 64;
#pragma unroll
        for (int i = 0; i < 4; i++) {
            int idx2 = tid + i * 128;
            int row = idx2 >> 3, c = (idx2 & 7) * 8;
            const uint32_t d = (uint32_t)(row * AT_STR + c) * 2;
            const size_t gk = (size_t)(bT + kb + row) * H + c;
            cp16(sb + KH_E * 2 + d, g_kh + gk);
            cp16(sb + KL_E * 2 + d, g_kl + gk);
            const size_t gv = (size_t)row * NROW + bT + kb + c;   // row = h
            cp16(sb + VH_E * 2 + d, g_vth + gv);
            cp16(sb + VL_E * 2 + d, g_vtl + gv);
        }
        CP_COMMIT();
    };

    load_q();
    load_kv(0, start);
    CP_COMMIT();
    if (start + 1 < end) load_kv(1, start + 1);

    uint32_t qfh[4][4], qfl[4][4];
    float o[8][4] = {};
    float m0 = -1e30f, m1 = -1e30f, l0 = 0.0f, l1 = 0.0f;
    const int r0loc = 16 * wid + g2;

    for (int j = start; j < end; j++) {
        if (j < end - 1) CP_WAIT1(); else CP_WAIT0();
        __syncthreads();

        if (j == start) {
#pragma unroll
            for (int kf = 0; kf < 4; kf++) {
                const uint32_t base =
                    (uint32_t)((16 * wid) * AT_STR + kf * 16) * 2 + aoff;
                ldsm4(qfh[kf], su + QH_E * 2 + base);
                ldsm4(qfl[kf], su + QL_E * 2 + base);
            }
        }

        const uint32_t sb = su + STG_E((j - start) & 1) * 2;

        // ---- S = Q K^T ----
        float sa[8][4] = {};
#pragma unroll
        for (int kf = 0; kf < 4; kf++) {
            uint32_t bh[16], bl[16];
#pragma unroll
            for (int n2 = 0; n2 < 4; n2++) {
                const uint32_t base =
                    (uint32_t)((n2 * 16) * AT_STR + kf * 16) * 2 + boff;
                ldsm4(bh + n2 * 4, sb + KH_E * 2 + base);
                ldsm4(bl + n2 * 4, sb + KL_E * 2 + base);
            }
#pragma unroll
            for (int nf = 0; nf < 8; nf++) {
                mma_bf16(sa[nf], qfh[kf], bh + nf * 2);
                mma_bf16(sa[nf], qfh[kf], bl + nf * 2);
                mma_bf16(sa[nf], qfl[kf], bh + nf * 2);
            }
        }

        // ---- causal mask (diag tile only; kBase == qBase there) ----
        if (j == qt) {
#pragma unroll
            for (int nf = 0; nf < 8; nf++) {
                const int n0 = nf * 8 + t2;
                if (n0     > r0loc)     sa[nf][0] = -1e30f;
                if (n0 + 1 > r0loc)     sa[nf][1] = -1e30f;
                if (n0     > r0loc + 8) sa[nf][2] = -1e30f;
                if (n0 + 1 > r0loc + 8) sa[nf][3] = -1e30f;
            }
        }

        // ---- online softmax (log2 domain; QSCALE folded into Q) ----
        float mx0 = -1e30f, mx1 = -1e30f;
#pragma unroll
        for (int nf = 0; nf < 8; nf++) {
            mx0 = fmaxf(mx0, fmaxf(sa[nf][0], sa[nf][1]));
            mx1 = fmaxf(mx1, fmaxf(sa[nf][2], sa[nf][3]));
        }
        mx0 = fmaxf(mx0, __shfl_xor_sync(0xffffffffu, mx0, 1));
        mx0 = fmaxf(mx0, __shfl_xor_sync(0xffffffffu, mx0, 2));
        mx1 = fmaxf(mx1, __shfl_xor_sync(0xffffffffu, mx1, 1));
        mx1 = fmaxf(mx1, __shfl_xor_sync(0xffffffffu, mx1, 2));
        const float mn0 = fmaxf(m0, mx0);
        const float mn1 = fmaxf(m1, mx1);
        const float corr0 = exp2f(m0 - mn0);
        const float corr1 = exp2f(m1 - mn1);

        uint32_t pah[4][4], pal[4][4];
        float rs0 = 0.0f, rs1 = 0.0f;
#pragma unroll
        for (int nf = 0; nf < 8; nf++) {
            const float p0 = exp2f(sa[nf][0] - mn0);
            const float p1 = exp2f(sa[nf][1] - mn0);
            const float p2 = exp2f(sa[nf][2] - mn1);
            const float p3 = exp2f(sa[nf][3] - mn1);
            rs0 += p0 + p1;
            rs1 += p2 + p3;
            __nv_bfloat16 h0, h1, h2, h3, lo0, lo1, lo2, lo3;
            split1(p0, h0, lo0); split1(p1, h1, lo1);
            split1(p2, h2, lo2); split1(p3, h3, lo3);
            const int kf = nf >> 1;
            const int rb = (nf & 1) * 2;
            pah[kf][rb]     = bf2pack(h0, h1);
            pah[kf][rb + 1] = bf2pack(h2, h3);
            pal[kf][rb]     = bf2pack(lo0, lo1);
            pal[kf][rb + 1] = bf2pack(lo2, lo3);
        }
        rs0 += __shfl_xor_sync(0xffffffffu, rs0, 1);
        rs0 += __shfl_xor_sync(0xffffffffu, rs0, 2);
        rs1 += __shfl_xor_sync(0xffffffffu, rs1, 1);
        rs1 += __shfl_xor_sync(0xffffffffu, rs1, 2);
        l0 = l0 * corr0 + rs0;
        l1 = l1 * corr1 + rs1;
        m0 = mn0;
        m1 = mn1;
#pragma unroll
        for (int hf = 0; hf < 8; hf++) {
            o[hf][0] *= corr0; o[hf][1] *= corr0;
            o[hf][2] *= corr1; o[hf][3] *= corr1;
        }

        // ---- O += P Vt^T ----
#pragma unroll
        for (int kf = 0; kf < 4; kf++) {
            uint32_t vh[16], vl[16];
#pragma unroll
            for (int n2 = 0; n2 < 4; n2++) {
                const uint32_t base =
                    (uint32_t)((n2 * 16) * AT_STR + kf * 16) * 2 + boff;
                ldsm4(vh + n2 * 4, sb + VH_E * 2 + base);
                ldsm4(vl + n2 * 4, sb + VL_E * 2 + base);
            }
#pragma unroll
            for (int hf = 0; hf < 8; hf++) {
                mma_bf16(o[hf], pah[kf], vh + hf * 2);
                mma_bf16(o[hf], pah[kf], vl + hf * 2);
                mma_bf16(o[hf], pal[kf], vh + hf * 2);
            }
        }

        if (j + 2 < end) {
            __syncthreads();
            load_kv((j - start) & 1, j + 2);
        }
    }

    // ---- epilogue: unnormalized partials + stats ----
    const size_t row0 = (size_t)s * NROW + bT + qBase + 16 * wid + g2;
#pragma unroll
    for (int hf = 0; hf < 8; hf++) {
        const int col = hf * 8 + t2;
        *(float2*)(g_po + row0 * H + col)       = {o[hf][0], o[hf][1]};
        *(float2*)(g_po + (row0 + 8) * H + col) = {o[hf][2], o[hf][3]};
    }
    if ((lane & 3) == 0) {
        g_pm[row0]     = m0;  g_pl[row0]     = l0;
        g_pm[row0 + 8] = m1;  g_pl[row0 + 8] = l1;
    }
}

// ---------------------------------------------------------------------------
// Kernel 3: merge the two split-K partials into the final output.
// ---------------------------------------------------------------------------
__global__ __launch_bounds__(256) void combine(float* __restrict__ out) {
    const int idx = blockIdx.x * 256 + threadIdx.x;   // NROW*16 = 131072
    const int row = idx >> 4, c4 = idx & 15;
    const float m0 = g_pm[row], m1 = g_pm[NROW + row];
    const float l0 = g_pl[row], l1 = g_pl[NROW + row];
    const float M = fmaxf(m0, m1);
    float w0 = exp2f(m0 - M), w1 = exp2f(m1 - M);
    const float inv = 1.0f / (l0 * w0 + l1 * w1);
    w0 *= inv; w1 *= inv;
    const float4 a = *(const float4*)(g_po + (size_t)row * H + c4 * 4);
    const float4 b = *(const float4*)(g_po + (size_t)(NROW + row) * H + c4 * 4);
    float4 o = {a.x * w0 + b.x * w1, a.y * w0 + b.y * w1,
                a.z * w0 + b.z * w1, a.w * w0 + b.w * w1};
    *(float4*)(out + (size_t)row * H + c4 * 4) = o;
}

extern "C" void kernel_launch(void* const* d_in, const int* in_sizes, int n_in,
                              void* d_out, int out_size) {
    const float* x  = (const float*)d_in[0];
    const float* Wq = (const float*)d_in[1];
    const float* Wk = (const float*)d_in[2];
    const float* Wv = (const float*)d_in[3];
    float* out = (float*)d_out;

    cudaFuncSetAttribute(qkv_mma, cudaFuncAttributeMaxDynamicSharedMemorySize,
                         PROJ_SMEM);
    cudaFuncSetAttribute(attn_mma, cudaFuncAttributeMaxDynamicSharedMemorySize,
                         ATT_SMEM);

    convert_w<<<W4 / 256, 256>>>(Wq, Wk, Wv);
    qkv_mma<<<128, 256, PROJ_SMEM>>>(x);
    attn_mma<<<256, 128, ATT_SMEM>>>();
    combine<<<NROW * 16 / 256, 256>>>(out);
}